// round 8
// baseline (speedup 1.0000x reference)
#include <cuda_runtime.h>
#include <cuda_bf16.h>
#include <stdint.h>
#include <math.h>

#define S_SAMPLES 10
#define IN_DIM    512
#define HID_DIM   1024
#define OUT_DIM   512
#define BATCH     1024
#define NPARAMS   (HID_DIM*IN_DIM + OUT_DIM*HID_DIM)   // 1,048,576
#define N1        (HID_DIM*IN_DIM)                      // 524,288

// ---------------------------------------------------------------------------
// Scratch (device globals — no allocation allowed)
// ---------------------------------------------------------------------------
static __device__ float g_hm[S_SAMPLES * 10];
static __device__ __nv_bfloat16 g_xh[BATCH * IN_DIM];
static __device__ __nv_bfloat16 g_xl[BATCH * IN_DIM];
static __device__ __nv_bfloat16 g_th[(size_t)S_SAMPLES * NPARAMS];
static __device__ __nv_bfloat16 g_tl[(size_t)S_SAMPLES * NPARAMS];
static __device__ __nv_bfloat16 g_ah[(size_t)S_SAMPLES * BATCH * HID_DIM];
static __device__ __nv_bfloat16 g_al[(size_t)S_SAMPLES * BATCH * HID_DIM];

__device__ __forceinline__ float elu1(float v) { return v > 0.0f ? v : expm1f(v); }

// ---------------------------------------------------------------------------
// PTX helpers (portable: sm_80+ instructions only)
// ---------------------------------------------------------------------------
__device__ __forceinline__ uint32_t smem_u32(const void* p) {
    uint32_t a;
    asm("{ .reg .u64 t; cvta.to.shared.u64 t, %1; cvt.u32.u64 %0, t; }" : "=r"(a) : "l"(p));
    return a;
}
__device__ __forceinline__ void cp_async16(uint32_t smem_dst, const void* gmem_src) {
    asm volatile("cp.async.cg.shared.global [%0], [%1], 16;"
                 :: "r"(smem_dst), "l"(gmem_src));
}
__device__ __forceinline__ void cp_commit() {
    asm volatile("cp.async.commit_group;");
}
__device__ __forceinline__ void cp_wait1() {
    asm volatile("cp.async.wait_group 1;");
}
__device__ __forceinline__ void cp_wait0() {
    asm volatile("cp.async.wait_group 0;");
}
__device__ __forceinline__ void ldsm4(uint32_t* r, uint32_t addr) {
    asm volatile("ldmatrix.sync.aligned.m8n8.x4.shared.b16 {%0,%1,%2,%3}, [%4];"
                 : "=r"(r[0]), "=r"(r[1]), "=r"(r[2]), "=r"(r[3]) : "r"(addr));
}
__device__ __forceinline__ void mma16816(float* d, const uint32_t* a, const uint32_t* b) {
    asm volatile("mma.sync.aligned.m16n8k16.row.col.f32.bf16.bf16.f32 "
                 "{%0,%1,%2,%3}, {%4,%5,%6,%7}, {%8,%9}, {%0,%1,%2,%3};"
                 : "+f"(d[0]), "+f"(d[1]), "+f"(d[2]), "+f"(d[3])
                 : "r"(a[0]), "r"(a[1]), "r"(a[2]), "r"(a[3]), "r"(b[0]), "r"(b[1]));
}

// ---------------------------------------------------------------------------
// Kernel 1: tiny hypernet trunk
// ---------------------------------------------------------------------------
__global__ void hyper_trunk_kernel(const float* __restrict__ z,
                                   const float* __restrict__ Wa,
                                   const float* __restrict__ Wb) {
    __shared__ float h1[S_SAMPLES * 10];
    int tid = threadIdx.x;
    if (tid < S_SAMPLES * 10) {
        int s = tid / 10, w = tid % 10;
        float acc = 0.0f;
        #pragma unroll
        for (int c = 0; c < 8; c++) acc += z[s*8 + c] * Wa[w*8 + c];
        h1[tid] = elu1(acc);
    }
    __syncthreads();
    if (tid < S_SAMPLES * 10) {
        int s = tid / 10, v = tid % 10;
        float acc = 0.0f;
        #pragma unroll
        for (int w = 0; w < 10; w++) acc += h1[s*10 + w] * Wb[v*10 + w];
        g_hm[s*10 + v] = elu1(acc);
    }
}

// ---------------------------------------------------------------------------
// Kernel 2: x -> bf16 hi/lo split
// ---------------------------------------------------------------------------
__global__ void xconv_kernel(const float* __restrict__ x) {
    int i4 = blockIdx.x * blockDim.x + threadIdx.x;
    if (i4 * 4 >= BATCH * IN_DIM) return;
    float4 v = reinterpret_cast<const float4*>(x)[i4];
    float f[4] = {v.x, v.y, v.z, v.w};
    __nv_bfloat16 h[4], l[4];
    #pragma unroll
    for (int j = 0; j < 4; j++) {
        h[j] = __float2bfloat16(f[j]);
        l[j] = __float2bfloat16(f[j] - __bfloat162float(h[j]));
    }
    __nv_bfloat162 h01 = __halves2bfloat162(h[0], h[1]);
    __nv_bfloat162 h23 = __halves2bfloat162(h[2], h[3]);
    __nv_bfloat162 l01 = __halves2bfloat162(l[0], l[1]);
    __nv_bfloat162 l23 = __halves2bfloat162(l[2], l[3]);
    reinterpret_cast<uint2*>(g_xh)[i4] = make_uint2(*(uint32_t*)&h01, *(uint32_t*)&h23);
    reinterpret_cast<uint2*>(g_xl)[i4] = make_uint2(*(uint32_t*)&l01, *(uint32_t*)&l23);
}

// ---------------------------------------------------------------------------
// Kernel 3: theta[s][p] = sum_v hm[s][v] * Wc[p][v] -> bf16 hi/lo
// ---------------------------------------------------------------------------
__global__ void theta_kernel(const float* __restrict__ Wc) {
    __shared__ float hm_s[S_SAMPLES * 10];
    if (threadIdx.x < S_SAMPLES * 10) hm_s[threadIdx.x] = g_hm[threadIdx.x];
    __syncthreads();

    int p0 = (blockIdx.x * blockDim.x + threadIdx.x) * 2;
    if (p0 >= NPARAMS) return;

    float wc0[10], wc1[10];
    #pragma unroll
    for (int v = 0; v < 10; v++) {
        wc0[v] = Wc[(size_t)p0 * 10 + v];
        wc1[v] = Wc[(size_t)(p0 + 1) * 10 + v];
    }
    #pragma unroll
    for (int s = 0; s < S_SAMPLES; s++) {
        float a0 = 0.0f, a1 = 0.0f;
        #pragma unroll
        for (int v = 0; v < 10; v++) {
            a0 += hm_s[s*10 + v] * wc0[v];
            a1 += hm_s[s*10 + v] * wc1[v];
        }
        __nv_bfloat16 h0 = __float2bfloat16(a0), h1 = __float2bfloat16(a1);
        __nv_bfloat16 l0 = __float2bfloat16(a0 - __bfloat162float(h0));
        __nv_bfloat16 l1 = __float2bfloat16(a1 - __bfloat162float(h1));
        __nv_bfloat162 hp = __halves2bfloat162(h0, h1);
        __nv_bfloat162 lp = __halves2bfloat162(l0, l1);
        *reinterpret_cast<uint32_t*>(g_th + (size_t)s * NPARAMS + p0) = *(uint32_t*)&hp;
        *reinterpret_cast<uint32_t*>(g_tl + (size_t)s * NPARAMS + p0) = *(uint32_t*)&lp;
    }
}

// ---------------------------------------------------------------------------
// Kernel 4: mma.sync NT GEMM with bf16-split (3 HMMA per product term).
// 128(M)x64(N) CTA tile, 8 warps (4Mx2N), warp tile 32x32, KC=32.
// 3-stage cp.async ring, ONE __syncthreads per chunk:
//   wait_group -> sync -> issue chunk c+2 -> compute chunk c.
// (Safe: the overwritten stage held chunk c-1, finished by every warp
//  before it arrived at this iteration's barrier.)
// SMS=40: 80B row stride — 16B-multiple (cp.async alignment) AND
// conflict-free for ldmatrix (20*r mod 32 covers all banks over 8 rows).
// Stage = (128+64) rows * 2 (hi,lo) * 80B = 30720B; 3 stages = 92160B/CTA.
// ---------------------------------------------------------------------------
#define KC      32
#define SMS     40                       // padded row stride (elems)
#define TA_E    (128 * SMS)              // A tile elems (5120)
#define TB_E    (64 * SMS)               // B tile elems (2560)
#define STAGE_E (2 * TA_E + 2 * TB_E)    // Ah, Al, Bh, Bl = 15360
#define STAGE_B (STAGE_E * 2)            // 30720 bytes
#define NSTAGE  3
#define SMEM_BYTES (NSTAGE * STAGE_B)    // 92160
// byte offsets within a stage
#define OFF_AH  0
#define OFF_AL  (TA_E * 2)
#define OFF_BH  (2 * TA_E * 2)
#define OFF_BL  (2 * TA_E * 2 + TB_E * 2)

template<int NC, bool LAYER1>
__global__ __launch_bounds__(256, 2)
void mma_gemm_kernel(const __nv_bfloat16* __restrict__ Ah_, const __nv_bfloat16* __restrict__ Al_,
                     unsigned long long sA, int lda,
                     const __nv_bfloat16* __restrict__ Bh_, const __nv_bfloat16* __restrict__ Bl_,
                     unsigned long long sB, int ldb,
                     float* __restrict__ Cf,
                     __nv_bfloat16* __restrict__ Ch, __nv_bfloat16* __restrict__ Cl,
                     unsigned long long sC, int ldc) {
    extern __shared__ __nv_bfloat16 sm[];
    const uint32_t smb = smem_u32(sm);
    const int tid  = threadIdx.x;
    const int lane = tid & 31, wid = tid >> 5;
    const int warpM = wid & 3, warpN = wid >> 2;
    const int s  = blockIdx.z;
    const int m0 = blockIdx.y * 128;
    const int n0 = blockIdx.x * 64;

    // Producer mapping.
    // A: 256 threads cover 128 rows x 2 half-rows of 16 elems; 2 cp16 each for Ah, Al.
    const int par = tid >> 1;               // 0..127
    const int pav = (tid & 1) * 16;         // 0 or 16
    const __nv_bfloat16* pAh = Ah_ + (size_t)s * sA + (size_t)(m0 + par) * lda + pav;
    const __nv_bfloat16* pAl = Al_ + (size_t)s * sA + (size_t)(m0 + par) * lda + pav;
    const uint32_t pdA = smb + (uint32_t)(par * SMS + pav) * 2;
    // B: 256 threads cover 64 rows x 4 eighths of 8 elems; 1 cp16 each for Bh, Bl.
    const int pbr = tid >> 2;               // 0..63
    const int pbv = (tid & 3) * 8;          // 0,8,16,24
    const __nv_bfloat16* pBh = Bh_ + (size_t)s * sB + (size_t)(n0 + pbr) * ldb + pbv;
    const __nv_bfloat16* pBl = Bl_ + (size_t)s * sB + (size_t)(n0 + pbr) * ldb + pbv;
    const uint32_t pdB = smb + (uint32_t)(pbr * SMS + pbv) * 2;

    // Consumer (ldmatrix) base addresses, hoisted.
    const uint32_t aOff = smb + (uint32_t)(((warpM * 32 + (lane & 15)) * SMS
                                            + ((lane >> 4) << 3)) * 2);
    const int rr = (lane & 7) + ((lane >> 4) & 1) * 8;
    const int kh = (lane >> 3) & 1;
    const uint32_t bOff = smb + OFF_BH
                        + (uint32_t)(((warpN * 32 + rr) * SMS + kh * 8) * 2);

    float acc[2][4][4];
    #pragma unroll
    for (int i = 0; i < 2; i++)
        #pragma unroll
        for (int j = 0; j < 4; j++)
            #pragma unroll
            for (int q = 0; q < 4; q++) acc[i][j][q] = 0.0f;

    auto issue = [&](int stage, int k0) {
        const uint32_t so = (uint32_t)stage * STAGE_B;
        #pragma unroll
        for (int v = 0; v < 16; v += 8) {
            cp_async16(pdA + so + OFF_AH + v * 2, pAh + k0 + v);
            cp_async16(pdA + so + OFF_AL + v * 2, pAl + k0 + v);
        }
        cp_async16(pdB + so + OFF_BH, pBh + k0);
        cp_async16(pdB + so + OFF_BL, pBl + k0);
        cp_commit();
    };

    issue(0, 0);
    issue(1, KC);

    int stageC = 0, stageP = 2;
    for (int c = 0; c < NC; c++) {
        if (c + 1 < NC) cp_wait1(); else cp_wait0();
        __syncthreads();
        if (c + 2 < NC) issue(stageP, (c + 2) * KC);

        const uint32_t aB = aOff + (uint32_t)stageC * STAGE_B;
        const uint32_t bB = bOff + (uint32_t)stageC * STAGE_B;
        #pragma unroll
        for (int ks = 0; ks < 2; ks++) {
            uint32_t afh[2][4], afl[2][4];
            #pragma unroll
            for (int i = 0; i < 2; i++) {
                uint32_t off = (uint32_t)((i * 16 * SMS + ks * 16) * 2);
                ldsm4(afh[i], aB + off);
                ldsm4(afl[i], aB + (OFF_AL - OFF_AH) + off);
            }
            #pragma unroll
            for (int j4 = 0; j4 < 2; j4++) {
                uint32_t off = (uint32_t)((j4 * 16 * SMS + ks * 16) * 2);
                uint32_t bh4[4], bl4[4];
                ldsm4(bh4, bB + off);
                ldsm4(bl4, bB + (OFF_BL - OFF_BH) + off);
                #pragma unroll
                for (int i = 0; i < 2; i++) {
                    mma16816(acc[i][2*j4],   afh[i], &bh4[0]);
                    mma16816(acc[i][2*j4],   afh[i], &bl4[0]);
                    mma16816(acc[i][2*j4],   afl[i], &bh4[0]);
                    mma16816(acc[i][2*j4+1], afh[i], &bh4[2]);
                    mma16816(acc[i][2*j4+1], afh[i], &bl4[2]);
                    mma16816(acc[i][2*j4+1], afl[i], &bh4[2]);
                }
            }
        }
        stageC = (stageC == NSTAGE - 1) ? 0 : stageC + 1;
        stageP = (stageP == NSTAGE - 1) ? 0 : stageP + 1;
    }

    // Epilogue. d0=(r,c), d1=(r,c+1), d2=(r+8,c), d3=(r+8,c+1);
    // r = lane>>2, c = (lane&3)*2.
    #pragma unroll
    for (int i = 0; i < 2; i++) {
        int gm = m0 + warpM * 32 + i * 16 + (lane >> 2);
        #pragma unroll
        for (int j = 0; j < 4; j++) {
            int gn = n0 + warpN * 32 + j * 8 + (lane & 3) * 2;
            float* d = acc[i][j];
            if (LAYER1) {
                #pragma unroll
                for (int half = 0; half < 2; half++) {
                    int r = gm + half * 8;
                    float v0 = elu1(d[half * 2 + 0]);
                    float v1 = elu1(d[half * 2 + 1]);
                    __nv_bfloat16 h0 = __float2bfloat16(v0), h1 = __float2bfloat16(v1);
                    __nv_bfloat16 l0 = __float2bfloat16(v0 - __bfloat162float(h0));
                    __nv_bfloat16 l1 = __float2bfloat16(v1 - __bfloat162float(h1));
                    __nv_bfloat162 hp = __halves2bfloat162(h0, h1);
                    __nv_bfloat162 lp = __halves2bfloat162(l0, l1);
                    size_t off = (size_t)s * sC + (size_t)r * ldc + gn;
                    *reinterpret_cast<uint32_t*>(Ch + off) = *(uint32_t*)&hp;
                    *reinterpret_cast<uint32_t*>(Cl + off) = *(uint32_t*)&lp;
                }
            } else {
                size_t off0 = (size_t)s * sC + (size_t)gm * ldc + gn;
                size_t off1 = (size_t)s * sC + (size_t)(gm + 8) * ldc + gn;
                *reinterpret_cast<float2*>(Cf + off0) = make_float2(d[0], d[1]);
                *reinterpret_cast<float2*>(Cf + off1) = make_float2(d[2], d[3]);
            }
        }
    }
}

// ---------------------------------------------------------------------------
// Launch
// Inputs: x [1024,512], z [10,8], Wa [10,8], Wb [10,10], Wc [1048576,10], samples
// Output: y [10, 1024, 512] fp32
// ---------------------------------------------------------------------------
extern "C" void kernel_launch(void* const* d_in, const int* in_sizes, int n_in,
                              void* d_out, int out_size) {
    const float* x  = (const float*)d_in[0];
    const float* z  = (const float*)d_in[1];
    const float* Wa = (const float*)d_in[2];
    const float* Wb = (const float*)d_in[3];
    const float* Wc = (const float*)d_in[4];
    float* out = (float*)d_out;
    (void)in_sizes; (void)n_in; (void)out_size;

    __nv_bfloat16 *xh, *xl, *th, *tl, *ah, *al;
    cudaGetSymbolAddress((void**)&xh, g_xh);
    cudaGetSymbolAddress((void**)&xl, g_xl);
    cudaGetSymbolAddress((void**)&th, g_th);
    cudaGetSymbolAddress((void**)&tl, g_tl);
    cudaGetSymbolAddress((void**)&ah, g_ah);
    cudaGetSymbolAddress((void**)&al, g_al);

    static bool attr_done = false;
    if (!attr_done) {
        cudaFuncSetAttribute(mma_gemm_kernel<16, true>,
                             cudaFuncAttributeMaxDynamicSharedMemorySize, SMEM_BYTES);
        cudaFuncSetAttribute(mma_gemm_kernel<32, false>,
                             cudaFuncAttributeMaxDynamicSharedMemorySize, SMEM_BYTES);
        attr_done = true;
    }

    // 1) trunk + x conversion (independent)
    hyper_trunk_kernel<<<1, 128>>>(z, Wa, Wb);
    xconv_kernel<<<(BATCH * IN_DIM / 4 + 255) / 256, 256>>>(x);

    // 2) theta -> bf16 hi/lo
    theta_kernel<<<(NPARAMS / 2 + 255) / 256, 256>>>(Wc);

    // 3) a[s] = elu(x @ W1[s]^T)  M=1024, N=1024, K=512  (NC = 16)
    {
        dim3 grid(HID_DIM / 64, BATCH / 128, S_SAMPLES);
        mma_gemm_kernel<16, true><<<grid, 256, SMEM_BYTES>>>(
            xh, xl, 0ull, IN_DIM,
            th, tl, (unsigned long long)NPARAMS, IN_DIM,
            nullptr, ah, al,
            (unsigned long long)(BATCH * HID_DIM), HID_DIM);
    }

    // 4) y[s] = a[s] @ W2[s]^T    M=1024, N=512, K=1024  (NC = 32)
    {
        dim3 grid(OUT_DIM / 64, BATCH / 128, S_SAMPLES);
        mma_gemm_kernel<32, false><<<grid, 256, SMEM_BYTES>>>(
            ah, al, (unsigned long long)(BATCH * HID_DIM), HID_DIM,
            th + N1, tl + N1, (unsigned long long)NPARAMS, HID_DIM,
            out, nullptr, nullptr,
            (unsigned long long)(BATCH * OUT_DIM), OUT_DIM);
    }
}

// round 11
// speedup vs baseline: 1.0724x; 1.0724x over previous
#include <cuda_runtime.h>
#include <cuda_bf16.h>
#include <stdint.h>
#include <math.h>

#define S_SAMPLES 10
#define IN_DIM    512
#define HID_DIM   1024
#define OUT_DIM   512
#define BATCH     1024
#define NPARAMS   (HID_DIM*IN_DIM + OUT_DIM*HID_DIM)   // 1,048,576
#define N1        (HID_DIM*IN_DIM)                      // 524,288

#define L1_TILES_PER_S 64     // (1024/128)*(1024/128)
#define L2_TILES_PER_S 32     // (1024/128)*(512/128)
#define L1_CTAS (S_SAMPLES * L1_TILES_PER_S)   // 640
#define L2_CTAS (S_SAMPLES * L2_TILES_PER_S)   // 320

// ---------------------------------------------------------------------------
// Scratch (device globals — no allocation allowed)
// ---------------------------------------------------------------------------
static __device__ float g_hm[S_SAMPLES * 10];
static __device__ int   g_cnt[S_SAMPLES];
static __device__ __nv_bfloat16 g_xh[BATCH * IN_DIM];
static __device__ __nv_bfloat16 g_xl[BATCH * IN_DIM];
static __device__ __nv_bfloat16 g_th[(size_t)S_SAMPLES * NPARAMS];
static __device__ __nv_bfloat16 g_tl[(size_t)S_SAMPLES * NPARAMS];
static __device__ __nv_bfloat16 g_ah[(size_t)S_SAMPLES * BATCH * HID_DIM];
static __device__ __nv_bfloat16 g_al[(size_t)S_SAMPLES * BATCH * HID_DIM];

__device__ __forceinline__ float elu1(float v) { return v > 0.0f ? v : expm1f(v); }

// ---------------------------------------------------------------------------
// PTX helpers (portable: sm_80+ instructions only)
// ---------------------------------------------------------------------------
__device__ __forceinline__ uint32_t smem_u32(const void* p) {
    uint32_t a;
    asm("{ .reg .u64 t; cvta.to.shared.u64 t, %1; cvt.u32.u64 %0, t; }" : "=r"(a) : "l"(p));
    return a;
}
__device__ __forceinline__ void cp_async16(uint32_t smem_dst, const void* gmem_src) {
    asm volatile("cp.async.cg.shared.global [%0], [%1], 16;"
                 :: "r"(smem_dst), "l"(gmem_src));
}
__device__ __forceinline__ void cp_commit() {
    asm volatile("cp.async.commit_group;");
}
__device__ __forceinline__ void cp_wait0() {
    asm volatile("cp.async.wait_group 0;");
}
__device__ __forceinline__ void ldsm4(uint32_t* r, uint32_t addr) {
    asm volatile("ldmatrix.sync.aligned.m8n8.x4.shared.b16 {%0,%1,%2,%3}, [%4];"
                 : "=r"(r[0]), "=r"(r[1]), "=r"(r[2]), "=r"(r[3]) : "r"(addr));
}
__device__ __forceinline__ void mma16816(float* d, const uint32_t* a, const uint32_t* b) {
    asm volatile("mma.sync.aligned.m16n8k16.row.col.f32.bf16.bf16.f32 "
                 "{%0,%1,%2,%3}, {%4,%5,%6,%7}, {%8,%9}, {%0,%1,%2,%3};"
                 : "+f"(d[0]), "+f"(d[1]), "+f"(d[2]), "+f"(d[3])
                 : "r"(a[0]), "r"(a[1]), "r"(a[2]), "r"(a[3]), "r"(b[0]), "r"(b[1]));
}

// ---------------------------------------------------------------------------
// Kernel 1: tiny hypernet trunk
// ---------------------------------------------------------------------------
__global__ void hyper_trunk_kernel(const float* __restrict__ z,
                                   const float* __restrict__ Wa,
                                   const float* __restrict__ Wb) {
    __shared__ float h1[S_SAMPLES * 10];
    int tid = threadIdx.x;
    if (tid < S_SAMPLES * 10) {
        int s = tid / 10, w = tid % 10;
        float acc = 0.0f;
        #pragma unroll
        for (int c = 0; c < 8; c++) acc += z[s*8 + c] * Wa[w*8 + c];
        h1[tid] = elu1(acc);
    }
    __syncthreads();
    if (tid < S_SAMPLES * 10) {
        int s = tid / 10, v = tid % 10;
        float acc = 0.0f;
        #pragma unroll
        for (int w = 0; w < 10; w++) acc += h1[s*10 + w] * Wb[v*10 + w];
        g_hm[s*10 + v] = elu1(acc);
    }
}

// ---------------------------------------------------------------------------
// Kernel 2: x -> bf16 hi/lo split
// ---------------------------------------------------------------------------
__global__ void xconv_kernel(const float* __restrict__ x) {
    int i4 = blockIdx.x * blockDim.x + threadIdx.x;
    if (i4 * 4 >= BATCH * IN_DIM) return;
    float4 v = reinterpret_cast<const float4*>(x)[i4];
    float f[4] = {v.x, v.y, v.z, v.w};
    __nv_bfloat16 h[4], l[4];
    #pragma unroll
    for (int j = 0; j < 4; j++) {
        h[j] = __float2bfloat16(f[j]);
        l[j] = __float2bfloat16(f[j] - __bfloat162float(h[j]));
    }
    __nv_bfloat162 h01 = __halves2bfloat162(h[0], h[1]);
    __nv_bfloat162 h23 = __halves2bfloat162(h[2], h[3]);
    __nv_bfloat162 l01 = __halves2bfloat162(l[0], l[1]);
    __nv_bfloat162 l23 = __halves2bfloat162(l[2], l[3]);
    reinterpret_cast<uint2*>(g_xh)[i4] = make_uint2(*(uint32_t*)&h01, *(uint32_t*)&h23);
    reinterpret_cast<uint2*>(g_xl)[i4] = make_uint2(*(uint32_t*)&l01, *(uint32_t*)&l23);
}

// ---------------------------------------------------------------------------
// Kernel 3: theta -> bf16 hi/lo. Also zeroes the layer1-completion counters
// (runs before the fused GEMM on the same stream every launch/replay).
// ---------------------------------------------------------------------------
__global__ void theta_kernel(const float* __restrict__ Wc) {
    if (blockIdx.x == 0 && threadIdx.x < S_SAMPLES) g_cnt[threadIdx.x] = 0;

    __shared__ float hm_s[S_SAMPLES * 10];
    if (threadIdx.x < S_SAMPLES * 10) hm_s[threadIdx.x] = g_hm[threadIdx.x];
    __syncthreads();

    int p0 = (blockIdx.x * blockDim.x + threadIdx.x) * 2;
    if (p0 >= NPARAMS) return;

    float wc0[10], wc1[10];
    #pragma unroll
    for (int v = 0; v < 10; v++) {
        wc0[v] = Wc[(size_t)p0 * 10 + v];
        wc1[v] = Wc[(size_t)(p0 + 1) * 10 + v];
    }
    #pragma unroll
    for (int s = 0; s < S_SAMPLES; s++) {
        float a0 = 0.0f, a1 = 0.0f;
        #pragma unroll
        for (int v = 0; v < 10; v++) {
            a0 += hm_s[s*10 + v] * wc0[v];
            a1 += hm_s[s*10 + v] * wc1[v];
        }
        __nv_bfloat16 h0 = __float2bfloat16(a0), h1 = __float2bfloat16(a1);
        __nv_bfloat16 l0 = __float2bfloat16(a0 - __bfloat162float(h0));
        __nv_bfloat16 l1 = __float2bfloat16(a1 - __bfloat162float(h1));
        __nv_bfloat162 hp = __halves2bfloat162(h0, h1);
        __nv_bfloat162 lp = __halves2bfloat162(l0, l1);
        *reinterpret_cast<uint32_t*>(g_th + (size_t)s * NPARAMS + p0) = *(uint32_t*)&hp;
        *reinterpret_cast<uint32_t*>(g_tl + (size_t)s * NPARAMS + p0) = *(uint32_t*)&lp;
    }
}

// ---------------------------------------------------------------------------
// Fused GEMM kernel: one flat grid of 960 CTAs.
//   bx in [0, 640):   layer1 tile — a[s] = elu(x @ W1[s]^T), K=512 (16 chunks)
//   bx in [640, 960): layer2 tile — y[s] = a[s] @ W2[s]^T,  K=1024 (32 chunks)
// Layer2 CTAs spin on g_cnt[s]==64 before their first load. Deadlock-free:
// the work distributor dispatches CTAs in linear order, so a resident
// consumer implies every producer is already dispatched; producers never wait.
//
// GEMM body: mma.sync NT, bf16-split (3 HMMA per product), 128x128 CTA tile,
// 8 warps (4Mx2N), warp tile 32x64, KC=32, 2-stage cp.async, one
// __syncthreads per chunk (wait0 -> sync -> issue c+1 -> compute c).
// SMS=40: 80B stride (16B-multiple for cp.async; conflict-free ldmatrix).
// ---------------------------------------------------------------------------
#define KC      32
#define SMS     40
#define TILE_E  (128 * SMS)              // 5120 elems per tile
#define STAGE_B (4 * TILE_E * 2)         // 40960 B: Ah, Al, Bh, Bl
#define SMEM_BYTES (2 * STAGE_B)         // 81920
#define OFF_AL  (TILE_E * 2)
#define OFF_BH  (2 * TILE_E * 2)
#define OFF_BL  (3 * TILE_E * 2)

__global__ __launch_bounds__(256, 2)
void fused_gemm_kernel(const __nv_bfloat16* __restrict__ xh,
                       const __nv_bfloat16* __restrict__ xl,
                       const __nv_bfloat16* __restrict__ th,
                       const __nv_bfloat16* __restrict__ tl,
                       __nv_bfloat16* __restrict__ ah,
                       __nv_bfloat16* __restrict__ al,
                       float* __restrict__ out) {
    extern __shared__ __nv_bfloat16 sm[];
    const uint32_t smb = smem_u32(sm);
    const int tid  = threadIdx.x;
    const int lane = tid & 31, wid = tid >> 5;
    const int warpM = wid & 3, warpN = wid >> 2;
    const int bx = blockIdx.x;
    const bool L1 = bx < L1_CTAS;

    int s, m0, n0, lda, ldb, ldc, NC;
    const __nv_bfloat16 *Ah_, *Al_, *Bh_, *Bl_;
    __nv_bfloat16 *Ch = nullptr, *Cl = nullptr;
    float* Cf = nullptr;

    if (L1) {
        s = bx / L1_TILES_PER_S;
        int t = bx % L1_TILES_PER_S;
        m0 = (t >> 3) * 128;  n0 = (t & 7) * 128;
        Ah_ = xh;  Al_ = xl;  lda = IN_DIM;
        Bh_ = th + (size_t)s * NPARAMS;  Bl_ = tl + (size_t)s * NPARAMS;  ldb = IN_DIM;
        Ch = ah + (size_t)s * BATCH * HID_DIM;
        Cl = al + (size_t)s * BATCH * HID_DIM;
        ldc = HID_DIM;  NC = 16;
    } else {
        int idx = bx - L1_CTAS;
        s = idx / L2_TILES_PER_S;
        int t = idx % L2_TILES_PER_S;
        m0 = (t >> 2) * 128;  n0 = (t & 3) * 128;
        Ah_ = ah + (size_t)s * BATCH * HID_DIM;
        Al_ = al + (size_t)s * BATCH * HID_DIM;  lda = HID_DIM;
        Bh_ = th + (size_t)s * NPARAMS + N1;
        Bl_ = tl + (size_t)s * NPARAMS + N1;     ldb = HID_DIM;
        Cf = out + (size_t)s * BATCH * OUT_DIM;
        ldc = OUT_DIM;  NC = 32;

        // Wait for this sample's layer1 to complete before any load.
        if (tid == 0) {
            while (*(volatile int*)&g_cnt[s] < L1_TILES_PER_S) __nanosleep(128);
        }
        __syncthreads();
        __threadfence();   // acquire: order subsequent loads after the flag read
    }

    // Producer mapping: 256 threads cover 128 rows x 2 half-rows of 16 elems.
    const int par = tid >> 1;
    const int pav = (tid & 1) * 16;
    const __nv_bfloat16* pAh = Ah_ + (size_t)(m0 + par) * lda + pav;
    const __nv_bfloat16* pAl = Al_ + (size_t)(m0 + par) * lda + pav;
    const __nv_bfloat16* pBh = Bh_ + (size_t)(n0 + par) * ldb + pav;
    const __nv_bfloat16* pBl = Bl_ + (size_t)(n0 + par) * ldb + pav;
    const uint32_t pdst = smb + (uint32_t)(par * SMS + pav) * 2;

    // Consumer (ldmatrix) base addresses, hoisted.
    const uint32_t aOff = smb + (uint32_t)(((warpM * 32 + (lane & 15)) * SMS
                                            + ((lane >> 4) << 3)) * 2);
    const int rr = (lane & 7) + ((lane >> 4) & 1) * 8;
    const int kh = (lane >> 3) & 1;
    const uint32_t bOff = smb + OFF_BH
                        + (uint32_t)(((warpN * 64 + rr) * SMS + kh * 8) * 2);

    float acc[2][8][4];
    #pragma unroll
    for (int i = 0; i < 2; i++)
        #pragma unroll
        for (int j = 0; j < 8; j++)
            #pragma unroll
            for (int q = 0; q < 4; q++) acc[i][j][q] = 0.0f;

    auto issue = [&](int stage, int k0) {
        const uint32_t d = pdst + (uint32_t)stage * STAGE_B;
        #pragma unroll
        for (int v = 0; v < 16; v += 8) {
            cp_async16(d + v * 2,          pAh + k0 + v);
            cp_async16(d + OFF_AL + v * 2, pAl + k0 + v);
            cp_async16(d + OFF_BH + v * 2, pBh + k0 + v);
            cp_async16(d + OFF_BL + v * 2, pBl + k0 + v);
        }
        cp_commit();
    };

    issue(0, 0);

    for (int c = 0; c < NC; c++) {
        cp_wait0();
        __syncthreads();
        if (c + 1 < NC) issue((c + 1) & 1, (c + 1) * KC);

        const uint32_t aB = aOff + (uint32_t)(c & 1) * STAGE_B;
        const uint32_t bB = bOff + (uint32_t)(c & 1) * STAGE_B;
        #pragma unroll
        for (int ks = 0; ks < 2; ks++) {
            uint32_t afh[2][4], afl[2][4];
            #pragma unroll
            for (int i = 0; i < 2; i++) {
                uint32_t off = (uint32_t)((i * 16 * SMS + ks * 16) * 2);
                ldsm4(afh[i], aB + off);
                ldsm4(afl[i], aB + OFF_AL + off);
            }
            #pragma unroll
            for (int j4 = 0; j4 < 4; j4++) {
                uint32_t off = (uint32_t)((j4 * 16 * SMS + ks * 16) * 2);
                uint32_t bh4[4], bl4[4];
                ldsm4(bh4, bB + off);
                ldsm4(bl4, bB + (OFF_BL - OFF_BH) + off);
                #pragma unroll
                for (int i = 0; i < 2; i++) {
                    mma16816(acc[i][2*j4],   afh[i], &bh4[0]);
                    mma16816(acc[i][2*j4],   afh[i], &bl4[0]);
                    mma16816(acc[i][2*j4],   afl[i], &bh4[0]);
                    mma16816(acc[i][2*j4+1], afh[i], &bh4[2]);
                    mma16816(acc[i][2*j4+1], afh[i], &bl4[2]);
                    mma16816(acc[i][2*j4+1], afl[i], &bh4[2]);
                }
            }
        }
    }

    // Epilogue. d0=(r,c), d1=(r,c+1), d2=(r+8,c), d3=(r+8,c+1);
    // r = lane>>2, c = (lane&3)*2.
    #pragma unroll
    for (int i = 0; i < 2; i++) {
        int gm = m0 + warpM * 32 + i * 16 + (lane >> 2);
        #pragma unroll
        for (int j = 0; j < 8; j++) {
            int gn = n0 + warpN * 64 + j * 8 + (lane & 3) * 2;
            float* d = acc[i][j];
            if (L1) {
                #pragma unroll
                for (int half = 0; half < 2; half++) {
                    int r = gm + half * 8;
                    float v0 = elu1(d[half * 2 + 0]);
                    float v1 = elu1(d[half * 2 + 1]);
                    __nv_bfloat16 h0 = __float2bfloat16(v0), h1 = __float2bfloat16(v1);
                    __nv_bfloat16 l0 = __float2bfloat16(v0 - __bfloat162float(h0));
                    __nv_bfloat16 l1 = __float2bfloat16(v1 - __bfloat162float(h1));
                    __nv_bfloat162 hp = __halves2bfloat162(h0, h1);
                    __nv_bfloat162 lp = __halves2bfloat162(l0, l1);
                    size_t off = (size_t)r * ldc + gn;
                    *reinterpret_cast<uint32_t*>(Ch + off) = *(uint32_t*)&hp;
                    *reinterpret_cast<uint32_t*>(Cl + off) = *(uint32_t*)&lp;
                }
            } else {
                size_t off0 = (size_t)gm * ldc + gn;
                size_t off1 = (size_t)(gm + 8) * ldc + gn;
                *reinterpret_cast<float2*>(Cf + off0) = make_float2(d[0], d[1]);
                *reinterpret_cast<float2*>(Cf + off1) = make_float2(d[2], d[3]);
            }
        }
    }

    // Producer publishes completion for its sample.
    if (L1) {
        __syncthreads();
        __threadfence();
        if (tid == 0) atomicAdd(&g_cnt[s], 1);
    }
}

// ---------------------------------------------------------------------------
// Launch
// Inputs: x [1024,512], z [10,8], Wa [10,8], Wb [10,10], Wc [1048576,10], samples
// Output: y [10, 1024, 512] fp32
// ---------------------------------------------------------------------------
extern "C" void kernel_launch(void* const* d_in, const int* in_sizes, int n_in,
                              void* d_out, int out_size) {
    const float* x  = (const float*)d_in[0];
    const float* z  = (const float*)d_in[1];
    const float* Wa = (const float*)d_in[2];
    const float* Wb = (const float*)d_in[3];
    const float* Wc = (const float*)d_in[4];
    float* out = (float*)d_out;
    (void)in_sizes; (void)n_in; (void)out_size;

    __nv_bfloat16 *xh, *xl, *th, *tl, *ah, *al;
    cudaGetSymbolAddress((void**)&xh, g_xh);
    cudaGetSymbolAddress((void**)&xl, g_xl);
    cudaGetSymbolAddress((void**)&th, g_th);
    cudaGetSymbolAddress((void**)&tl, g_tl);
    cudaGetSymbolAddress((void**)&ah, g_ah);
    cudaGetSymbolAddress((void**)&al, g_al);

    static bool attr_done = false;
    if (!attr_done) {
        cudaFuncSetAttribute(fused_gemm_kernel,
                             cudaFuncAttributeMaxDynamicSharedMemorySize, SMEM_BYTES);
        attr_done = true;
    }

    hyper_trunk_kernel<<<1, 128>>>(z, Wa, Wb);
    xconv_kernel<<<(BATCH * IN_DIM / 4 + 255) / 256, 256>>>(x);
    theta_kernel<<<(NPARAMS / 2 + 255) / 256, 256>>>(Wc);

    fused_gemm_kernel<<<L1_CTAS + L2_CTAS, 256, SMEM_BYTES>>>(
        xh, xl, th, tl, ah, al, out);
}

// round 12
// speedup vs baseline: 1.1175x; 1.0421x over previous
#include <cuda_runtime.h>
#include <cuda_bf16.h>
#include <stdint.h>
#include <math.h>

#define S_SAMPLES 10
#define IN_DIM    512
#define HID_DIM   1024
#define OUT_DIM   512
#define BATCH     1024
#define NPARAMS   (HID_DIM*IN_DIM + OUT_DIM*HID_DIM)   // 1,048,576
#define N1        (HID_DIM*IN_DIM)                      // 524,288

// Tile geometry: 64(M) x 128(N) CTA tile, warp tile 32x32 (2M x 4N warps).
#define L1_TILES_PER_S ((BATCH/64) * (HID_DIM/128))   // 16*8 = 128
#define L2_TILES_PER_S ((BATCH/64) * (OUT_DIM/128))   // 16*4 = 64
#define L1_CTAS (S_SAMPLES * L1_TILES_PER_S)          // 1280
#define L2_CTAS (S_SAMPLES * L2_TILES_PER_S)          // 640

// ---------------------------------------------------------------------------
// Scratch (device globals — no allocation allowed)
// ---------------------------------------------------------------------------
static __device__ float g_hm[S_SAMPLES * 10];
static __device__ int   g_cnt[S_SAMPLES];
static __device__ __nv_bfloat16 g_xh[BATCH * IN_DIM];
static __device__ __nv_bfloat16 g_xl[BATCH * IN_DIM];
static __device__ __nv_bfloat16 g_th[(size_t)S_SAMPLES * NPARAMS];
static __device__ __nv_bfloat16 g_tl[(size_t)S_SAMPLES * NPARAMS];
static __device__ __nv_bfloat16 g_ah[(size_t)S_SAMPLES * BATCH * HID_DIM];
static __device__ __nv_bfloat16 g_al[(size_t)S_SAMPLES * BATCH * HID_DIM];

__device__ __forceinline__ float elu1(float v) { return v > 0.0f ? v : expm1f(v); }

// ---------------------------------------------------------------------------
// PTX helpers (portable: sm_80+ instructions only)
// ---------------------------------------------------------------------------
__device__ __forceinline__ uint32_t smem_u32(const void* p) {
    uint32_t a;
    asm("{ .reg .u64 t; cvta.to.shared.u64 t, %1; cvt.u32.u64 %0, t; }" : "=r"(a) : "l"(p));
    return a;
}
__device__ __forceinline__ void cp_async16(uint32_t smem_dst, const void* gmem_src) {
    asm volatile("cp.async.cg.shared.global [%0], [%1], 16;"
                 :: "r"(smem_dst), "l"(gmem_src));
}
__device__ __forceinline__ void cp_commit() {
    asm volatile("cp.async.commit_group;");
}
__device__ __forceinline__ void cp_wait0() {
    asm volatile("cp.async.wait_group 0;");
}
__device__ __forceinline__ void ldsm4(uint32_t* r, uint32_t addr) {
    asm volatile("ldmatrix.sync.aligned.m8n8.x4.shared.b16 {%0,%1,%2,%3}, [%4];"
                 : "=r"(r[0]), "=r"(r[1]), "=r"(r[2]), "=r"(r[3]) : "r"(addr));
}
__device__ __forceinline__ void mma16816(float* d, const uint32_t* a, const uint32_t* b) {
    asm volatile("mma.sync.aligned.m16n8k16.row.col.f32.bf16.bf16.f32 "
                 "{%0,%1,%2,%3}, {%4,%5,%6,%7}, {%8,%9}, {%0,%1,%2,%3};"
                 : "+f"(d[0]), "+f"(d[1]), "+f"(d[2]), "+f"(d[3])
                 : "r"(a[0]), "r"(a[1]), "r"(a[2]), "r"(a[3]), "r"(b[0]), "r"(b[1]));
}

// ---------------------------------------------------------------------------
// Kernel 1: tiny hypernet trunk
// ---------------------------------------------------------------------------
__global__ void hyper_trunk_kernel(const float* __restrict__ z,
                                   const float* __restrict__ Wa,
                                   const float* __restrict__ Wb) {
    __shared__ float h1[S_SAMPLES * 10];
    int tid = threadIdx.x;
    if (tid < S_SAMPLES * 10) {
        int s = tid / 10, w = tid % 10;
        float acc = 0.0f;
        #pragma unroll
        for (int c = 0; c < 8; c++) acc += z[s*8 + c] * Wa[w*8 + c];
        h1[tid] = elu1(acc);
    }
    __syncthreads();
    if (tid < S_SAMPLES * 10) {
        int s = tid / 10, v = tid % 10;
        float acc = 0.0f;
        #pragma unroll
        for (int w = 0; w < 10; w++) acc += h1[s*10 + w] * Wb[v*10 + w];
        g_hm[s*10 + v] = elu1(acc);
    }
}

// ---------------------------------------------------------------------------
// Kernel 2: x -> bf16 hi/lo split
// ---------------------------------------------------------------------------
__global__ void xconv_kernel(const float* __restrict__ x) {
    int i4 = blockIdx.x * blockDim.x + threadIdx.x;
    if (i4 * 4 >= BATCH * IN_DIM) return;
    float4 v = reinterpret_cast<const float4*>(x)[i4];
    float f[4] = {v.x, v.y, v.z, v.w};
    __nv_bfloat16 h[4], l[4];
    #pragma unroll
    for (int j = 0; j < 4; j++) {
        h[j] = __float2bfloat16(f[j]);
        l[j] = __float2bfloat16(f[j] - __bfloat162float(h[j]));
    }
    __nv_bfloat162 h01 = __halves2bfloat162(h[0], h[1]);
    __nv_bfloat162 h23 = __halves2bfloat162(h[2], h[3]);
    __nv_bfloat162 l01 = __halves2bfloat162(l[0], l[1]);
    __nv_bfloat162 l23 = __halves2bfloat162(l[2], l[3]);
    reinterpret_cast<uint2*>(g_xh)[i4] = make_uint2(*(uint32_t*)&h01, *(uint32_t*)&h23);
    reinterpret_cast<uint2*>(g_xl)[i4] = make_uint2(*(uint32_t*)&l01, *(uint32_t*)&l23);
}

// ---------------------------------------------------------------------------
// Kernel 3: theta -> bf16 hi/lo. Also zeroes layer1-completion counters.
// ---------------------------------------------------------------------------
__global__ void theta_kernel(const float* __restrict__ Wc) {
    if (blockIdx.x == 0 && threadIdx.x < S_SAMPLES) g_cnt[threadIdx.x] = 0;

    __shared__ float hm_s[S_SAMPLES * 10];
    if (threadIdx.x < S_SAMPLES * 10) hm_s[threadIdx.x] = g_hm[threadIdx.x];
    __syncthreads();

    int p0 = (blockIdx.x * blockDim.x + threadIdx.x) * 2;
    if (p0 >= NPARAMS) return;

    float wc0[10], wc1[10];
    #pragma unroll
    for (int v = 0; v < 10; v++) {
        wc0[v] = Wc[(size_t)p0 * 10 + v];
        wc1[v] = Wc[(size_t)(p0 + 1) * 10 + v];
    }
    #pragma unroll
    for (int s = 0; s < S_SAMPLES; s++) {
        float a0 = 0.0f, a1 = 0.0f;
        #pragma unroll
        for (int v = 0; v < 10; v++) {
            a0 += hm_s[s*10 + v] * wc0[v];
            a1 += hm_s[s*10 + v] * wc1[v];
        }
        __nv_bfloat16 h0 = __float2bfloat16(a0), h1 = __float2bfloat16(a1);
        __nv_bfloat16 l0 = __float2bfloat16(a0 - __bfloat162float(h0));
        __nv_bfloat16 l1 = __float2bfloat16(a1 - __bfloat162float(h1));
        __nv_bfloat162 hp = __halves2bfloat162(h0, h1);
        __nv_bfloat162 lp = __halves2bfloat162(l0, l1);
        *reinterpret_cast<uint32_t*>(g_th + (size_t)s * NPARAMS + p0) = *(uint32_t*)&hp;
        *reinterpret_cast<uint32_t*>(g_tl + (size_t)s * NPARAMS + p0) = *(uint32_t*)&lp;
    }
}

// ---------------------------------------------------------------------------
// Fused GEMM kernel: one flat grid of 1920 CTAs.
//   bx in [0, 1280):    layer1 tile — a[s] = elu(x @ W1[s]^T), K=512 (16 chunks)
//   bx in [1280, 1920): layer2 tile — y[s] = a[s] @ W2[s]^T,  K=1024 (32 chunks)
// Layer2 CTAs spin on g_cnt[s]==128 before their first load. Deadlock-free by
// linear dispatch order.
//
// GEMM body: mma.sync NT, bf16-split (3 HMMA per product), 64x128 CTA tile,
// 8 warps (2Mx4N), warp tile 32x32, KC=32, 2-stage cp.async, one
// __syncthreads per chunk, 3 CTAs/SM (launch_bounds(256,3)).
// SMS=40: 80B stride (16B-multiple for cp.async; conflict-free ldmatrix).
// Stage = (64+128) rows * 2 (hi,lo) * 80B = 30720B; 2 stages = 61440B/CTA.
// ---------------------------------------------------------------------------
#define KC      32
#define SMS     40
#define TA_E    (64 * SMS)               // A tile elems (2560)
#define TB_E    (128 * SMS)              // B tile elems (5120)
#define STAGE_B ((2 * TA_E + 2 * TB_E) * 2)   // 30720 B
#define SMEM_BYTES (2 * STAGE_B)              // 61440
#define OFF_AL  (TA_E * 2)
#define OFF_BH  (2 * TA_E * 2)
#define OFF_BL  (2 * TA_E * 2 + TB_E * 2)

__global__ __launch_bounds__(256, 3)
void fused_gemm_kernel(const __nv_bfloat16* __restrict__ xh,
                       const __nv_bfloat16* __restrict__ xl,
                       const __nv_bfloat16* __restrict__ th,
                       const __nv_bfloat16* __restrict__ tl,
                       __nv_bfloat16* __restrict__ ah,
                       __nv_bfloat16* __restrict__ al,
                       float* __restrict__ out) {
    extern __shared__ __nv_bfloat16 sm[];
    const uint32_t smb = smem_u32(sm);
    const int tid  = threadIdx.x;
    const int lane = tid & 31, wid = tid >> 5;
    const int warpM = wid & 1, warpN = wid >> 1;   // 2M x 4N
    const int bx = blockIdx.x;
    const bool L1 = bx < L1_CTAS;

    int s, m0, n0, lda, ldb, ldc, NC;
    const __nv_bfloat16 *Ah_, *Al_, *Bh_, *Bl_;
    __nv_bfloat16 *Ch = nullptr, *Cl = nullptr;
    float* Cf = nullptr;

    if (L1) {
        s = bx / L1_TILES_PER_S;
        int t = bx % L1_TILES_PER_S;
        m0 = (t >> 3) * 64;  n0 = (t & 7) * 128;
        Ah_ = xh;  Al_ = xl;  lda = IN_DIM;
        Bh_ = th + (size_t)s * NPARAMS;  Bl_ = tl + (size_t)s * NPARAMS;  ldb = IN_DIM;
        Ch = ah + (size_t)s * BATCH * HID_DIM;
        Cl = al + (size_t)s * BATCH * HID_DIM;
        ldc = HID_DIM;  NC = 16;
    } else {
        int idx = bx - L1_CTAS;
        s = idx / L2_TILES_PER_S;
        int t = idx % L2_TILES_PER_S;
        m0 = (t >> 2) * 64;  n0 = (t & 3) * 128;
        Ah_ = ah + (size_t)s * BATCH * HID_DIM;
        Al_ = al + (size_t)s * BATCH * HID_DIM;  lda = HID_DIM;
        Bh_ = th + (size_t)s * NPARAMS + N1;
        Bl_ = tl + (size_t)s * NPARAMS + N1;     ldb = HID_DIM;
        Cf = out + (size_t)s * BATCH * OUT_DIM;
        ldc = OUT_DIM;  NC = 32;

        // Wait for this sample's layer1 to complete before any load.
        if (tid == 0) {
            while (*(volatile int*)&g_cnt[s] < L1_TILES_PER_S) __nanosleep(128);
        }
        __syncthreads();
        __threadfence();   // acquire: order subsequent loads after the flag read
    }

    // Producer mapping.
    // A: 256 threads cover 64 rows x 4 col-chunks of 8 elems; 1 cp16 per hi/lo.
    const int par = tid >> 2;               // 0..63
    const int pav = (tid & 3) * 8;          // 0,8,16,24
    const __nv_bfloat16* pAh = Ah_ + (size_t)(m0 + par) * lda + pav;
    const __nv_bfloat16* pAl = Al_ + (size_t)(m0 + par) * lda + pav;
    const uint32_t pdA = smb + (uint32_t)(par * SMS + pav) * 2;
    // B: 256 threads cover 128 rows x 2 halves of 16 elems; 2 cp16 per hi/lo.
    const int pbr = tid >> 1;               // 0..127
    const int pbv = (tid & 1) * 16;         // 0 or 16
    const __nv_bfloat16* pBh = Bh_ + (size_t)(n0 + pbr) * ldb + pbv;
    const __nv_bfloat16* pBl = Bl_ + (size_t)(n0 + pbr) * ldb + pbv;
    const uint32_t pdB = smb + (uint32_t)(pbr * SMS + pbv) * 2;

    // Consumer (ldmatrix) base addresses, hoisted.
    const uint32_t aOff = smb + (uint32_t)(((warpM * 32 + (lane & 15)) * SMS
                                            + ((lane >> 4) << 3)) * 2);
    const int rr = (lane & 7) + ((lane >> 4) & 1) * 8;
    const int kh = (lane >> 3) & 1;
    const uint32_t bOff = smb + OFF_BH
                        + (uint32_t)(((warpN * 32 + rr) * SMS + kh * 8) * 2);

    float acc[2][4][4];
    #pragma unroll
    for (int i = 0; i < 2; i++)
        #pragma unroll
        for (int j = 0; j < 4; j++)
            #pragma unroll
            for (int q = 0; q < 4; q++) acc[i][j][q] = 0.0f;

    auto issue = [&](int stage, int k0) {
        const uint32_t so = (uint32_t)stage * STAGE_B;
        cp_async16(pdA + so,          pAh + k0);
        cp_async16(pdA + so + OFF_AL, pAl + k0);
        #pragma unroll
        for (int v = 0; v < 16; v += 8) {
            cp_async16(pdB + so + OFF_BH + v * 2, pBh + k0 + v);
            cp_async16(pdB + so + OFF_BL + v * 2, pBl + k0 + v);
        }
        cp_commit();
    };

    issue(0, 0);

    for (int c = 0; c < NC; c++) {
        cp_wait0();
        __syncthreads();
        if (c + 1 < NC) issue((c + 1) & 1, (c + 1) * KC);

        const uint32_t aB = aOff + (uint32_t)(c & 1) * STAGE_B;
        const uint32_t bB = bOff + (uint32_t)(c & 1) * STAGE_B;
        #pragma unroll
        for (int ks = 0; ks < 2; ks++) {
            uint32_t afh[2][4], afl[2][4];
            #pragma unroll
            for (int i = 0; i < 2; i++) {
                uint32_t off = (uint32_t)((i * 16 * SMS + ks * 16) * 2);
                ldsm4(afh[i], aB + off);
                ldsm4(afl[i], aB + OFF_AL + off);
            }
            #pragma unroll
            for (int j4 = 0; j4 < 2; j4++) {
                uint32_t off = (uint32_t)((j4 * 16 * SMS + ks * 16) * 2);
                uint32_t bh4[4], bl4[4];
                ldsm4(bh4, bB + off);
                ldsm4(bl4, bB + (OFF_BL - OFF_BH) + off);
                #pragma unroll
                for (int i = 0; i < 2; i++) {
                    mma16816(acc[i][2*j4],   afh[i], &bh4[0]);
                    mma16816(acc[i][2*j4],   afh[i], &bl4[0]);
                    mma16816(acc[i][2*j4],   afl[i], &bh4[0]);
                    mma16816(acc[i][2*j4+1], afh[i], &bh4[2]);
                    mma16816(acc[i][2*j4+1], afh[i], &bl4[2]);
                    mma16816(acc[i][2*j4+1], afl[i], &bh4[2]);
                }
            }
        }
    }

    // Epilogue. d0=(r,c), d1=(r,c+1), d2=(r+8,c), d3=(r+8,c+1);
    // r = lane>>2, c = (lane&3)*2.
    #pragma unroll
    for (int i = 0; i < 2; i++) {
        int gm = m0 + warpM * 32 + i * 16 + (lane >> 2);
        #pragma unroll
        for (int j = 0; j < 4; j++) {
            int gn = n0 + warpN * 32 + j * 8 + (lane & 3) * 2;
            float* d = acc[i][j];
            if (L1) {
                #pragma unroll
                for (int half = 0; half < 2; half++) {
                    int r = gm + half * 8;
                    float v0 = elu1(d[half * 2 + 0]);
                    float v1 = elu1(d[half * 2 + 1]);
                    __nv_bfloat16 h0 = __float2bfloat16(v0), h1 = __float2bfloat16(v1);
                    __nv_bfloat16 l0 = __float2bfloat16(v0 - __bfloat162float(h0));
                    __nv_bfloat16 l1 = __float2bfloat16(v1 - __bfloat162float(h1));
                    __nv_bfloat162 hp = __halves2bfloat162(h0, h1);
                    __nv_bfloat162 lp = __halves2bfloat162(l0, l1);
                    size_t off = (size_t)r * ldc + gn;
                    *reinterpret_cast<uint32_t*>(Ch + off) = *(uint32_t*)&hp;
                    *reinterpret_cast<uint32_t*>(Cl + off) = *(uint32_t*)&lp;
                }
            } else {
                size_t off0 = (size_t)gm * ldc + gn;
                size_t off1 = (size_t)(gm + 8) * ldc + gn;
                *reinterpret_cast<float2*>(Cf + off0) = make_float2(d[0], d[1]);
                *reinterpret_cast<float2*>(Cf + off1) = make_float2(d[2], d[3]);
            }
        }
    }

    // Producer publishes completion for its sample.
    if (L1) {
        __syncthreads();
        __threadfence();
        if (tid == 0) atomicAdd(&g_cnt[s], 1);
    }
}

// ---------------------------------------------------------------------------
// Launch
// Inputs: x [1024,512], z [10,8], Wa [10,8], Wb [10,10], Wc [1048576,10], samples
// Output: y [10, 1024, 512] fp32
// ---------------------------------------------------------------------------
extern "C" void kernel_launch(void* const* d_in, const int* in_sizes, int n_in,
                              void* d_out, int out_size) {
    const float* x  = (const float*)d_in[0];
    const float* z  = (const float*)d_in[1];
    const float* Wa = (const float*)d_in[2];
    const float* Wb = (const float*)d_in[3];
    const float* Wc = (const float*)d_in[4];
    float* out = (float*)d_out;
    (void)in_sizes; (void)n_in; (void)out_size;

    __nv_bfloat16 *xh, *xl, *th, *tl, *ah, *al;
    cudaGetSymbolAddress((void**)&xh, g_xh);
    cudaGetSymbolAddress((void**)&xl, g_xl);
    cudaGetSymbolAddress((void**)&th, g_th);
    cudaGetSymbolAddress((void**)&tl, g_tl);
    cudaGetSymbolAddress((void**)&ah, g_ah);
    cudaGetSymbolAddress((void**)&al, g_al);

    static bool attr_done = false;
    if (!attr_done) {
        cudaFuncSetAttribute(fused_gemm_kernel,
                             cudaFuncAttributeMaxDynamicSharedMemorySize, SMEM_BYTES);
        attr_done = true;
    }

    hyper_trunk_kernel<<<1, 128>>>(z, Wa, Wb);
    xconv_kernel<<<(BATCH * IN_DIM / 4 + 255) / 256, 256>>>(x);
    theta_kernel<<<(NPARAMS / 2 + 255) / 256, 256>>>(Wc);

    fused_gemm_kernel<<<L1_CTAS + L2_CTAS, 256, SMEM_BYTES>>>(
        xh, xl, th, tl, ah, al, out);
}

// round 13
// speedup vs baseline: 1.1210x; 1.0031x over previous
#include <cuda_runtime.h>
#include <cuda_bf16.h>
#include <stdint.h>
#include <math.h>

#define S_SAMPLES 10
#define IN_DIM    512
#define HID_DIM   1024
#define OUT_DIM   512
#define BATCH     1024
#define NPARAMS   (HID_DIM*IN_DIM + OUT_DIM*HID_DIM)   // 1,048,576
#define N1        (HID_DIM*IN_DIM)                      // 524,288

// Tile geometry: 64(M) x 128(N) CTA tile, warp tile 32x32 (2M x 4N warps).
#define L1_TILES_PER_S ((BATCH/64) * (HID_DIM/128))   // 16*8 = 128
#define L2_TILES_PER_S ((BATCH/64) * (OUT_DIM/128))   // 16*4 = 64
#define L1_CTAS (S_SAMPLES * L1_TILES_PER_S)          // 1280
#define L2_CTAS (S_SAMPLES * L2_TILES_PER_S)          // 640

// ---------------------------------------------------------------------------
// Scratch (device globals — no allocation allowed)
// ---------------------------------------------------------------------------
static __device__ float g_hm[S_SAMPLES * 10];
static __device__ int   g_cnt[S_SAMPLES];
static __device__ __nv_bfloat16 g_xh[BATCH * IN_DIM];
static __device__ __nv_bfloat16 g_xl[BATCH * IN_DIM];
static __device__ __nv_bfloat16 g_th[(size_t)S_SAMPLES * NPARAMS];
static __device__ __nv_bfloat16 g_tl[(size_t)S_SAMPLES * NPARAMS];
static __device__ __nv_bfloat16 g_ah[(size_t)S_SAMPLES * BATCH * HID_DIM];
static __device__ __nv_bfloat16 g_al[(size_t)S_SAMPLES * BATCH * HID_DIM];

__device__ __forceinline__ float elu1(float v) { return v > 0.0f ? v : expm1f(v); }

// ---------------------------------------------------------------------------
// PTX helpers (portable: sm_80+ instructions only)
// ---------------------------------------------------------------------------
__device__ __forceinline__ uint32_t smem_u32(const void* p) {
    uint32_t a;
    asm("{ .reg .u64 t; cvta.to.shared.u64 t, %1; cvt.u32.u64 %0, t; }" : "=r"(a) : "l"(p));
    return a;
}
__device__ __forceinline__ void cp_async16(uint32_t smem_dst, const void* gmem_src) {
    asm volatile("cp.async.cg.shared.global [%0], [%1], 16;"
                 :: "r"(smem_dst), "l"(gmem_src));
}
__device__ __forceinline__ void cp_commit() {
    asm volatile("cp.async.commit_group;");
}
__device__ __forceinline__ void cp_wait0() {
    asm volatile("cp.async.wait_group 0;");
}
__device__ __forceinline__ void ldsm4(uint32_t* r, uint32_t addr) {
    asm volatile("ldmatrix.sync.aligned.m8n8.x4.shared.b16 {%0,%1,%2,%3}, [%4];"
                 : "=r"(r[0]), "=r"(r[1]), "=r"(r[2]), "=r"(r[3]) : "r"(addr));
}
__device__ __forceinline__ void mma16816(float* d, const uint32_t* a, const uint32_t* b) {
    asm volatile("mma.sync.aligned.m16n8k16.row.col.f32.bf16.bf16.f32 "
                 "{%0,%1,%2,%3}, {%4,%5,%6,%7}, {%8,%9}, {%0,%1,%2,%3};"
                 : "+f"(d[0]), "+f"(d[1]), "+f"(d[2]), "+f"(d[3])
                 : "r"(a[0]), "r"(a[1]), "r"(a[2]), "r"(a[3]), "r"(b[0]), "r"(b[1]));
}

// ---------------------------------------------------------------------------
// Kernel 1: tiny hypernet trunk
// ---------------------------------------------------------------------------
__global__ void hyper_trunk_kernel(const float* __restrict__ z,
                                   const float* __restrict__ Wa,
                                   const float* __restrict__ Wb) {
    __shared__ float h1[S_SAMPLES * 10];
    int tid = threadIdx.x;
    if (tid < S_SAMPLES * 10) {
        int s = tid / 10, w = tid % 10;
        float acc = 0.0f;
        #pragma unroll
        for (int c = 0; c < 8; c++) acc += z[s*8 + c] * Wa[w*8 + c];
        h1[tid] = elu1(acc);
    }
    __syncthreads();
    if (tid < S_SAMPLES * 10) {
        int s = tid / 10, v = tid % 10;
        float acc = 0.0f;
        #pragma unroll
        for (int w = 0; w < 10; w++) acc += h1[s*10 + w] * Wb[v*10 + w];
        g_hm[s*10 + v] = elu1(acc);
    }
}

// ---------------------------------------------------------------------------
// Kernel 2: x -> bf16 hi/lo split
// ---------------------------------------------------------------------------
__global__ void xconv_kernel(const float* __restrict__ x) {
    int i4 = blockIdx.x * blockDim.x + threadIdx.x;
    if (i4 * 4 >= BATCH * IN_DIM) return;
    float4 v = reinterpret_cast<const float4*>(x)[i4];
    float f[4] = {v.x, v.y, v.z, v.w};
    __nv_bfloat16 h[4], l[4];
    #pragma unroll
    for (int j = 0; j < 4; j++) {
        h[j] = __float2bfloat16(f[j]);
        l[j] = __float2bfloat16(f[j] - __bfloat162float(h[j]));
    }
    __nv_bfloat162 h01 = __halves2bfloat162(h[0], h[1]);
    __nv_bfloat162 h23 = __halves2bfloat162(h[2], h[3]);
    __nv_bfloat162 l01 = __halves2bfloat162(l[0], l[1]);
    __nv_bfloat162 l23 = __halves2bfloat162(l[2], l[3]);
    reinterpret_cast<uint2*>(g_xh)[i4] = make_uint2(*(uint32_t*)&h01, *(uint32_t*)&h23);
    reinterpret_cast<uint2*>(g_xl)[i4] = make_uint2(*(uint32_t*)&l01, *(uint32_t*)&l23);
}

// ---------------------------------------------------------------------------
// Kernel 3: theta -> bf16 hi/lo. Also zeroes layer1-completion counters.
// ---------------------------------------------------------------------------
__global__ void theta_kernel(const float* __restrict__ Wc) {
    if (blockIdx.x == 0 && threadIdx.x < S_SAMPLES) g_cnt[threadIdx.x] = 0;

    __shared__ float hm_s[S_SAMPLES * 10];
    if (threadIdx.x < S_SAMPLES * 10) hm_s[threadIdx.x] = g_hm[threadIdx.x];
    __syncthreads();

    int p0 = (blockIdx.x * blockDim.x + threadIdx.x) * 2;
    if (p0 >= NPARAMS) return;

    float wc0[10], wc1[10];
    #pragma unroll
    for (int v = 0; v < 10; v++) {
        wc0[v] = Wc[(size_t)p0 * 10 + v];
        wc1[v] = Wc[(size_t)(p0 + 1) * 10 + v];
    }
    #pragma unroll
    for (int s = 0; s < S_SAMPLES; s++) {
        float a0 = 0.0f, a1 = 0.0f;
        #pragma unroll
        for (int v = 0; v < 10; v++) {
            a0 += hm_s[s*10 + v] * wc0[v];
            a1 += hm_s[s*10 + v] * wc1[v];
        }
        __nv_bfloat16 h0 = __float2bfloat16(a0), h1 = __float2bfloat16(a1);
        __nv_bfloat16 l0 = __float2bfloat16(a0 - __bfloat162float(h0));
        __nv_bfloat16 l1 = __float2bfloat16(a1 - __bfloat162float(h1));
        __nv_bfloat162 hp = __halves2bfloat162(h0, h1);
        __nv_bfloat162 lp = __halves2bfloat162(l0, l1);
        *reinterpret_cast<uint32_t*>(g_th + (size_t)s * NPARAMS + p0) = *(uint32_t*)&hp;
        *reinterpret_cast<uint32_t*>(g_tl + (size_t)s * NPARAMS + p0) = *(uint32_t*)&lp;
    }
}

// ---------------------------------------------------------------------------
// Fused GEMM kernel: one flat grid of 1920 CTAs.
//   bx in [0, 1280):    layer1 tile — a[s] = elu(x @ W1[s]^T), K=512 (16 chunks)
//   bx in [1280, 1920): layer2 tile — y[s] = a[s] @ W2[s]^T,  K=1024 (32 chunks)
// Layer2 CTAs spin on g_cnt[s]==128 before their first load. Deadlock-free by
// linear dispatch order.
//
// GEMM body: mma.sync NT, bf16-split, 64x128 CTA tile, 8 warps (2Mx4N),
// warp tile 32x32, KC=32, 2-stage cp.async, one __syncthreads per chunk,
// 3 CTAs/SM. MMAs within each (ks, j4) block issued TERM-MAJOR so the
// same-accumulator reuse distance is 4 (was 1 — three back-to-back RAW
// HMMAs into one acc were the dominant stall).
// SMS=40: 80B stride (16B-multiple for cp.async; conflict-free ldmatrix).
// ---------------------------------------------------------------------------
#define KC      32
#define SMS     40
#define TA_E    (64 * SMS)               // A tile elems (2560)
#define TB_E    (128 * SMS)              // B tile elems (5120)
#define STAGE_B ((2 * TA_E + 2 * TB_E) * 2)   // 30720 B
#define SMEM_BYTES (2 * STAGE_B)              // 61440
#define OFF_AL  (TA_E * 2)
#define OFF_BH  (2 * TA_E * 2)
#define OFF_BL  (2 * TA_E * 2 + TB_E * 2)

__global__ __launch_bounds__(256, 3)
void fused_gemm_kernel(const __nv_bfloat16* __restrict__ xh,
                       const __nv_bfloat16* __restrict__ xl,
                       const __nv_bfloat16* __restrict__ th,
                       const __nv_bfloat16* __restrict__ tl,
                       __nv_bfloat16* __restrict__ ah,
                       __nv_bfloat16* __restrict__ al,
                       float* __restrict__ out) {
    extern __shared__ __nv_bfloat16 sm[];
    const uint32_t smb = smem_u32(sm);
    const int tid  = threadIdx.x;
    const int lane = tid & 31, wid = tid >> 5;
    const int warpM = wid & 1, warpN = wid >> 1;   // 2M x 4N
    const int bx = blockIdx.x;
    const bool L1 = bx < L1_CTAS;

    int s, m0, n0, lda, ldb, ldc, NC;
    const __nv_bfloat16 *Ah_, *Al_, *Bh_, *Bl_;
    __nv_bfloat16 *Ch = nullptr, *Cl = nullptr;
    float* Cf = nullptr;

    if (L1) {
        s = bx / L1_TILES_PER_S;
        int t = bx % L1_TILES_PER_S;
        m0 = (t >> 3) * 64;  n0 = (t & 7) * 128;
        Ah_ = xh;  Al_ = xl;  lda = IN_DIM;
        Bh_ = th + (size_t)s * NPARAMS;  Bl_ = tl + (size_t)s * NPARAMS;  ldb = IN_DIM;
        Ch = ah + (size_t)s * BATCH * HID_DIM;
        Cl = al + (size_t)s * BATCH * HID_DIM;
        ldc = HID_DIM;  NC = 16;
    } else {
        int idx = bx - L1_CTAS;
        s = idx / L2_TILES_PER_S;
        int t = idx % L2_TILES_PER_S;
        m0 = (t >> 2) * 64;  n0 = (t & 3) * 128;
        Ah_ = ah + (size_t)s * BATCH * HID_DIM;
        Al_ = al + (size_t)s * BATCH * HID_DIM;  lda = HID_DIM;
        Bh_ = th + (size_t)s * NPARAMS + N1;
        Bl_ = tl + (size_t)s * NPARAMS + N1;     ldb = HID_DIM;
        Cf = out + (size_t)s * BATCH * OUT_DIM;
        ldc = OUT_DIM;  NC = 32;

        // Wait for this sample's layer1 to complete before any load.
        if (tid == 0) {
            while (*(volatile int*)&g_cnt[s] < L1_TILES_PER_S) __nanosleep(128);
        }
        __syncthreads();
        __threadfence();   // acquire: order subsequent loads after the flag read
    }

    // Producer mapping.
    // A: 256 threads cover 64 rows x 4 col-chunks of 8 elems; 1 cp16 per hi/lo.
    const int par = tid >> 2;               // 0..63
    const int pav = (tid & 3) * 8;          // 0,8,16,24
    const __nv_bfloat16* pAh = Ah_ + (size_t)(m0 + par) * lda + pav;
    const __nv_bfloat16* pAl = Al_ + (size_t)(m0 + par) * lda + pav;
    const uint32_t pdA = smb + (uint32_t)(par * SMS + pav) * 2;
    // B: 256 threads cover 128 rows x 2 halves of 16 elems; 2 cp16 per hi/lo.
    const int pbr = tid >> 1;               // 0..127
    const int pbv = (tid & 1) * 16;         // 0 or 16
    const __nv_bfloat16* pBh = Bh_ + (size_t)(n0 + pbr) * ldb + pbv;
    const __nv_bfloat16* pBl = Bl_ + (size_t)(n0 + pbr) * ldb + pbv;
    const uint32_t pdB = smb + (uint32_t)(pbr * SMS + pbv) * 2;

    // Consumer (ldmatrix) base addresses, hoisted.
    const uint32_t aOff = smb + (uint32_t)(((warpM * 32 + (lane & 15)) * SMS
                                            + ((lane >> 4) << 3)) * 2);
    const int rr = (lane & 7) + ((lane >> 4) & 1) * 8;
    const int kh = (lane >> 3) & 1;
    const uint32_t bOff = smb + OFF_BH
                        + (uint32_t)(((warpN * 32 + rr) * SMS + kh * 8) * 2);

    float acc[2][4][4];
    #pragma unroll
    for (int i = 0; i < 2; i++)
        #pragma unroll
        for (int j = 0; j < 4; j++)
            #pragma unroll
            for (int q = 0; q < 4; q++) acc[i][j][q] = 0.0f;

    auto issue = [&](int stage, int k0) {
        const uint32_t so = (uint32_t)stage * STAGE_B;
        cp_async16(pdA + so,          pAh + k0);
        cp_async16(pdA + so + OFF_AL, pAl + k0);
        #pragma unroll
        for (int v = 0; v < 16; v += 8) {
            cp_async16(pdB + so + OFF_BH + v * 2, pBh + k0 + v);
            cp_async16(pdB + so + OFF_BL + v * 2, pBl + k0 + v);
        }
        cp_commit();
    };

    issue(0, 0);

    for (int c = 0; c < NC; c++) {
        cp_wait0();
        __syncthreads();
        if (c + 1 < NC) issue((c + 1) & 1, (c + 1) * KC);

        const uint32_t aB = aOff + (uint32_t)(c & 1) * STAGE_B;
        const uint32_t bB = bOff + (uint32_t)(c & 1) * STAGE_B;
        #pragma unroll
        for (int ks = 0; ks < 2; ks++) {
            uint32_t afh[2][4], afl[2][4];
            #pragma unroll
            for (int i = 0; i < 2; i++) {
                uint32_t off = (uint32_t)((i * 16 * SMS + ks * 16) * 2);
                ldsm4(afh[i], aB + off);
                ldsm4(afl[i], aB + OFF_AL + off);
            }
            #pragma unroll
            for (int j4 = 0; j4 < 2; j4++) {
                uint32_t off = (uint32_t)((j4 * 16 * SMS + ks * 16) * 2);
                uint32_t bh4[4], bl4[4];
                ldsm4(bh4, bB + off);
                ldsm4(bl4, bB + (OFF_BL - OFF_BH) + off);
                // Term-major issue order: same-acc reuse distance = 4
                // (was 1: three consecutive RAW HMMAs per accumulator).
                mma16816(acc[0][2*j4],   afh[0], &bh4[0]);
                mma16816(acc[0][2*j4+1], afh[0], &bh4[2]);
                mma16816(acc[1][2*j4],   afh[1], &bh4[0]);
                mma16816(acc[1][2*j4+1], afh[1], &bh4[2]);

                mma16816(acc[0][2*j4],   afh[0], &bl4[0]);
                mma16816(acc[0][2*j4+1], afh[0], &bl4[2]);
                mma16816(acc[1][2*j4],   afh[1], &bl4[0]);
                mma16816(acc[1][2*j4+1], afh[1], &bl4[2]);

                mma16816(acc[0][2*j4],   afl[0], &bh4[0]);
                mma16816(acc[0][2*j4+1], afl[0], &bh4[2]);
                mma16816(acc[1][2*j4],   afl[1], &bh4[0]);
                mma16816(acc[1][2*j4+1], afl[1], &bh4[2]);
            }
        }
    }

    // Epilogue. d0=(r,c), d1=(r,c+1), d2=(r+8,c), d3=(r+8,c+1);
    // r = lane>>2, c = (lane&3)*2.
    #pragma unroll
    for (int i = 0; i < 2; i++) {
        int gm = m0 + warpM * 32 + i * 16 + (lane >> 2);
        #pragma unroll
        for (int j = 0; j < 4; j++) {
            int gn = n0 + warpN * 32 + j * 8 + (lane & 3) * 2;
            float* d = acc[i][j];
            if (L1) {
                #pragma unroll
                for (int half = 0; half < 2; half++) {
                    int r = gm + half * 8;
                    float v0 = elu1(d[half * 2 + 0]);
                    float v1 = elu1(d[half * 2 + 1]);
                    __nv_bfloat16 h0 = __float2bfloat16(v0), h1 = __float2bfloat16(v1);
                    __nv_bfloat16 l0 = __float2bfloat16(v0 - __bfloat162float(h0));
                    __nv_bfloat16 l1 = __float2bfloat16(v1 - __bfloat162float(h1));
                    __nv_bfloat162 hp = __halves2bfloat162(h0, h1);
                    __nv_bfloat162 lp = __halves2bfloat162(l0, l1);
                    size_t off = (size_t)r * ldc + gn;
                    *reinterpret_cast<uint32_t*>(Ch + off) = *(uint32_t*)&hp;
                    *reinterpret_cast<uint32_t*>(Cl + off) = *(uint32_t*)&lp;
                }
            } else {
                size_t off0 = (size_t)gm * ldc + gn;
                size_t off1 = (size_t)(gm + 8) * ldc + gn;
                *reinterpret_cast<float2*>(Cf + off0) = make_float2(d[0], d[1]);
                *reinterpret_cast<float2*>(Cf + off1) = make_float2(d[2], d[3]);
            }
        }
    }

    // Producer publishes completion for its sample.
    if (L1) {
        __syncthreads();
        __threadfence();
        if (tid == 0) atomicAdd(&g_cnt[s], 1);
    }
}

// ---------------------------------------------------------------------------
// Launch
// Inputs: x [1024,512], z [10,8], Wa [10,8], Wb [10,10], Wc [1048576,10], samples
// Output: y [10, 1024, 512] fp32
// ---------------------------------------------------------------------------
extern "C" void kernel_launch(void* const* d_in, const int* in_sizes, int n_in,
                              void* d_out, int out_size) {
    const float* x  = (const float*)d_in[0];
    const float* z  = (const float*)d_in[1];
    const float* Wa = (const float*)d_in[2];
    const float* Wb = (const float*)d_in[3];
    const float* Wc = (const float*)d_in[4];
    float* out = (float*)d_out;
    (void)in_sizes; (void)n_in; (void)out_size;

    __nv_bfloat16 *xh, *xl, *th, *tl, *ah, *al;
    cudaGetSymbolAddress((void**)&xh, g_xh);
    cudaGetSymbolAddress((void**)&xl, g_xl);
    cudaGetSymbolAddress((void**)&th, g_th);
    cudaGetSymbolAddress((void**)&tl, g_tl);
    cudaGetSymbolAddress((void**)&ah, g_ah);
    cudaGetSymbolAddress((void**)&al, g_al);

    static bool attr_done = false;
    if (!attr_done) {
        cudaFuncSetAttribute(fused_gemm_kernel,
                             cudaFuncAttributeMaxDynamicSharedMemorySize, SMEM_BYTES);
        attr_done = true;
    }

    hyper_trunk_kernel<<<1, 128>>>(z, Wa, Wb);
    xconv_kernel<<<(BATCH * IN_DIM / 4 + 255) / 256, 256>>>(x);
    theta_kernel<<<(NPARAMS / 2 + 255) / 256, 256>>>(Wc);

    fused_gemm_kernel<<<L1_CTAS + L2_CTAS, 256, SMEM_BYTES>>>(
        xh, xl, th, tl, ah, al, out);
}

// round 15
// speedup vs baseline: 1.6583x; 1.4793x over previous
#include <cuda_runtime.h>
#include <cuda_fp16.h>
#include <stdint.h>
#include <math.h>

#define S_SAMPLES 10
#define IN_DIM    512
#define HID_DIM   1024
#define OUT_DIM   512
#define BATCH     1024
#define NPARAMS   (HID_DIM*IN_DIM + OUT_DIM*HID_DIM)   // 1,048,576
#define N1        (HID_DIM*IN_DIM)                      // 524,288

// Tile geometry: 64(M) x 128(N) CTA tile, warp tile 32x32 (2M x 4N warps).
#define L1_TILES_PER_S ((BATCH/64) * (HID_DIM/128))   // 128
#define L2_TILES_PER_S ((BATCH/64) * (OUT_DIM/128))   // 64
#define L1_CTAS (S_SAMPLES * L1_TILES_PER_S)          // 1280
#define L2_CTAS (S_SAMPLES * L2_TILES_PER_S)          // 640

// ---------------------------------------------------------------------------
// Scratch (device globals — no allocation allowed)
// A-side operands (x, a) stored as fp16 hi/lo pairs (split error ~2^-22).
// W (theta) stored as SINGLE fp16 (dominant error source, ~2.8e-4/layer).
// ---------------------------------------------------------------------------
static __device__ float g_hm[S_SAMPLES * 10];
static __device__ int   g_cnt[S_SAMPLES];
static __device__ __half g_xh[BATCH * IN_DIM];
static __device__ __half g_xl[BATCH * IN_DIM];
static __device__ __half g_th[(size_t)S_SAMPLES * NPARAMS];
static __device__ __half g_ah[(size_t)S_SAMPLES * BATCH * HID_DIM];
static __device__ __half g_al[(size_t)S_SAMPLES * BATCH * HID_DIM];

__device__ __forceinline__ float elu1(float v) { return v > 0.0f ? v : expm1f(v); }

// ---------------------------------------------------------------------------
// PTX helpers (portable: sm_80+ instructions only)
// ---------------------------------------------------------------------------
__device__ __forceinline__ uint32_t smem_u32(const void* p) {
    uint32_t a;
    asm("{ .reg .u64 t; cvta.to.shared.u64 t, %1; cvt.u32.u64 %0, t; }" : "=r"(a) : "l"(p));
    return a;
}
__device__ __forceinline__ void cp_async16(uint32_t smem_dst, const void* gmem_src) {
    asm volatile("cp.async.cg.shared.global [%0], [%1], 16;"
                 :: "r"(smem_dst), "l"(gmem_src));
}
__device__ __forceinline__ void cp_commit() {
    asm volatile("cp.async.commit_group;");
}
__device__ __forceinline__ void cp_wait0() {
    asm volatile("cp.async.wait_group 0;");
}
__device__ __forceinline__ void ldsm4(uint32_t* r, uint32_t addr) {
    asm volatile("ldmatrix.sync.aligned.m8n8.x4.shared.b16 {%0,%1,%2,%3}, [%4];"
                 : "=r"(r[0]), "=r"(r[1]), "=r"(r[2]), "=r"(r[3]) : "r"(addr));
}
__device__ __forceinline__ void mma16816(float* d, const uint32_t* a, const uint32_t* b) {
    asm volatile("mma.sync.aligned.m16n8k16.row.col.f32.f16.f16.f32 "
                 "{%0,%1,%2,%3}, {%4,%5,%6,%7}, {%8,%9}, {%0,%1,%2,%3};"
                 : "+f"(d[0]), "+f"(d[1]), "+f"(d[2]), "+f"(d[3])
                 : "r"(a[0]), "r"(a[1]), "r"(a[2]), "r"(a[3]), "r"(b[0]), "r"(b[1]));
}

// ---------------------------------------------------------------------------
// Kernel 1: tiny hypernet trunk
// ---------------------------------------------------------------------------
__global__ void hyper_trunk_kernel(const float* __restrict__ z,
                                   const float* __restrict__ Wa,
                                   const float* __restrict__ Wb) {
    __shared__ float h1[S_SAMPLES * 10];
    int tid = threadIdx.x;
    if (tid < S_SAMPLES * 10) {
        int s = tid / 10, w = tid % 10;
        float acc = 0.0f;
        #pragma unroll
        for (int c = 0; c < 8; c++) acc += z[s*8 + c] * Wa[w*8 + c];
        h1[tid] = elu1(acc);
    }
    __syncthreads();
    if (tid < S_SAMPLES * 10) {
        int s = tid / 10, v = tid % 10;
        float acc = 0.0f;
        #pragma unroll
        for (int w = 0; w < 10; w++) acc += h1[s*10 + w] * Wb[v*10 + w];
        g_hm[s*10 + v] = elu1(acc);
    }
}

// ---------------------------------------------------------------------------
// Kernel 2: x -> fp16 hi/lo split
// ---------------------------------------------------------------------------
__global__ void xconv_kernel(const float* __restrict__ x) {
    int i4 = blockIdx.x * blockDim.x + threadIdx.x;
    if (i4 * 4 >= BATCH * IN_DIM) return;
    float4 v = reinterpret_cast<const float4*>(x)[i4];
    float f[4] = {v.x, v.y, v.z, v.w};
    __half h[4], l[4];
    #pragma unroll
    for (int j = 0; j < 4; j++) {
        h[j] = __float2half_rn(f[j]);
        l[j] = __float2half_rn(f[j] - __half2float(h[j]));
    }
    __half2 h01 = __halves2half2(h[0], h[1]);
    __half2 h23 = __halves2half2(h[2], h[3]);
    __half2 l01 = __halves2half2(l[0], l[1]);
    __half2 l23 = __halves2half2(l[2], l[3]);
    reinterpret_cast<uint2*>(g_xh)[i4] = make_uint2(*(uint32_t*)&h01, *(uint32_t*)&h23);
    reinterpret_cast<uint2*>(g_xl)[i4] = make_uint2(*(uint32_t*)&l01, *(uint32_t*)&l23);
}

// ---------------------------------------------------------------------------
// Kernel 3: theta -> single fp16. Also zeroes layer1-completion counters.
// ---------------------------------------------------------------------------
__global__ void theta_kernel(const float* __restrict__ Wc) {
    if (blockIdx.x == 0 && threadIdx.x < S_SAMPLES) g_cnt[threadIdx.x] = 0;

    __shared__ float hm_s[S_SAMPLES * 10];
    if (threadIdx.x < S_SAMPLES * 10) hm_s[threadIdx.x] = g_hm[threadIdx.x];
    __syncthreads();

    int p0 = (blockIdx.x * blockDim.x + threadIdx.x) * 2;
    if (p0 >= NPARAMS) return;

    float wc0[10], wc1[10];
    #pragma unroll
    for (int v = 0; v < 10; v++) {
        wc0[v] = Wc[(size_t)p0 * 10 + v];
        wc1[v] = Wc[(size_t)(p0 + 1) * 10 + v];
    }
    #pragma unroll
    for (int s = 0; s < S_SAMPLES; s++) {
        float a0 = 0.0f, a1 = 0.0f;
        #pragma unroll
        for (int v = 0; v < 10; v++) {
            a0 += hm_s[s*10 + v] * wc0[v];
            a1 += hm_s[s*10 + v] * wc1[v];
        }
        __half2 hp = __halves2half2(__float2half_rn(a0), __float2half_rn(a1));
        *reinterpret_cast<uint32_t*>(g_th + (size_t)s * NPARAMS + p0) = *(uint32_t*)&hp;
    }
}

// ---------------------------------------------------------------------------
// Fused GEMM kernel: one flat grid of 1920 CTAs.
//   bx in [0, 1280):    layer1 tile — a[s] = elu(x @ W1[s]^T), K=512 (16 chunks)
//   bx in [1280, 1920): layer2 tile — y[s] = a[s] @ W2[s]^T,  K=1024 (32 chunks)
// Layer2 CTAs spin on g_cnt[s]==128 before their first load (deadlock-free by
// linear dispatch order).
//
// GEMM body: mma.sync NT fp16, 2-term split: a*b ~= ah*bh + al*bh
// (A split hi/lo, W single fp16). 64x128 CTA tile, 8 warps (2Mx4N),
// warp tile 32x32, KC=32, 2-stage cp.async, one __syncthreads per chunk,
// 3 CTAs/SM. SMS=40: 80B stride.
// B producer: each thread owns 16 halves (32B) -> TWO cp16 per stage
// (R14's single-copy bug left half of B uninitialized -> NaN).
// Stage = (64 hi + 64 lo + 128 B) rows * 80B = 20480B; 2 stages = 40960B/CTA.
// ---------------------------------------------------------------------------
#define KC      32
#define SMS     40
#define TA_E    (64 * SMS)               // A tile elems (2560)
#define TB_E    (128 * SMS)              // B tile elems (5120)
#define STAGE_B ((2 * TA_E + TB_E) * 2)  // 20480 B
#define SMEM_BYTES (2 * STAGE_B)         // 40960
#define OFF_AL  (TA_E * 2)
#define OFF_BH  (2 * TA_E * 2)

__global__ __launch_bounds__(256, 3)
void fused_gemm_kernel(const __half* __restrict__ xh,
                       const __half* __restrict__ xl,
                       const __half* __restrict__ th,
                       __half* __restrict__ ah,
                       __half* __restrict__ al,
                       float* __restrict__ out) {
    extern __shared__ __half sm[];
    const uint32_t smb = smem_u32(sm);
    const int tid  = threadIdx.x;
    const int lane = tid & 31, wid = tid >> 5;
    const int warpM = wid & 1, warpN = wid >> 1;   // 2M x 4N
    const int bx = blockIdx.x;
    const bool L1 = bx < L1_CTAS;

    int s, m0, n0, lda, ldb, ldc, NC;
    const __half *Ah_, *Al_, *Bh_;
    __half *Ch = nullptr, *Cl = nullptr;
    float* Cf = nullptr;

    if (L1) {
        s = bx / L1_TILES_PER_S;
        int t = bx % L1_TILES_PER_S;
        m0 = (t >> 3) * 64;  n0 = (t & 7) * 128;
        Ah_ = xh;  Al_ = xl;  lda = IN_DIM;
        Bh_ = th + (size_t)s * NPARAMS;  ldb = IN_DIM;
        Ch = ah + (size_t)s * BATCH * HID_DIM;
        Cl = al + (size_t)s * BATCH * HID_DIM;
        ldc = HID_DIM;  NC = 16;
    } else {
        int idx = bx - L1_CTAS;
        s = idx / L2_TILES_PER_S;
        int t = idx % L2_TILES_PER_S;
        m0 = (t >> 2) * 64;  n0 = (t & 3) * 128;
        Ah_ = ah + (size_t)s * BATCH * HID_DIM;
        Al_ = al + (size_t)s * BATCH * HID_DIM;  lda = HID_DIM;
        Bh_ = th + (size_t)s * NPARAMS + N1;     ldb = HID_DIM;
        Cf = out + (size_t)s * BATCH * OUT_DIM;
        ldc = OUT_DIM;  NC = 32;

        // Wait for this sample's layer1 to complete before any load.
        if (tid == 0) {
            while (*(volatile int*)&g_cnt[s] < L1_TILES_PER_S) __nanosleep(128);
        }
        __syncthreads();
        __threadfence();   // acquire: order subsequent loads after the flag read
    }

    // Producer mapping.
    // A: 256 threads cover 64 rows x 4 col-chunks of 8 elems; 1 cp16 per hi/lo.
    const int par = tid >> 2;               // 0..63
    const int pav = (tid & 3) * 8;          // 0,8,16,24
    const __half* pAh = Ah_ + (size_t)(m0 + par) * lda + pav;
    const __half* pAl = Al_ + (size_t)(m0 + par) * lda + pav;
    const uint32_t pdA = smb + (uint32_t)(par * SMS + pav) * 2;
    // B (single fp16): 256 threads cover 128 rows x 2 halves of 16 elems; 2 cp16.
    const int pbr = tid >> 1;               // 0..127
    const int pbv = (tid & 1) * 16;         // 0 or 16
    const __half* pBh = Bh_ + (size_t)(n0 + pbr) * ldb + pbv;
    const uint32_t pdB = smb + (uint32_t)(pbr * SMS + pbv) * 2;

    // Consumer (ldmatrix) base addresses, hoisted.
    const uint32_t aOff = smb + (uint32_t)(((warpM * 32 + (lane & 15)) * SMS
                                            + ((lane >> 4) << 3)) * 2);
    const int rr = (lane & 7) + ((lane >> 4) & 1) * 8;
    const int kh = (lane >> 3) & 1;
    const uint32_t bOff = smb + OFF_BH
                        + (uint32_t)(((warpN * 32 + rr) * SMS + kh * 8) * 2);

    float acc[2][4][4];
    #pragma unroll
    for (int i = 0; i < 2; i++)
        #pragma unroll
        for (int j = 0; j < 4; j++)
            #pragma unroll
            for (int q = 0; q < 4; q++) acc[i][j][q] = 0.0f;

    auto issue = [&](int stage, int k0) {
        const uint32_t so = (uint32_t)stage * STAGE_B;
        cp_async16(pdA + so,          pAh + k0);
        cp_async16(pdA + so + OFF_AL, pAl + k0);
        cp_async16(pdB + so + OFF_BH,      pBh + k0);
        cp_async16(pdB + so + OFF_BH + 16, pBh + k0 + 8);
        cp_commit();
    };

    issue(0, 0);

    for (int c = 0; c < NC; c++) {
        cp_wait0();
        __syncthreads();
        if (c + 1 < NC) issue((c + 1) & 1, (c + 1) * KC);

        const uint32_t aB = aOff + (uint32_t)(c & 1) * STAGE_B;
        const uint32_t bB = bOff + (uint32_t)(c & 1) * STAGE_B;
        #pragma unroll
        for (int ks = 0; ks < 2; ks++) {
            uint32_t afh[2][4], afl[2][4];
            #pragma unroll
            for (int i = 0; i < 2; i++) {
                uint32_t off = (uint32_t)((i * 16 * SMS + ks * 16) * 2);
                ldsm4(afh[i], aB + off);
                ldsm4(afl[i], aB + OFF_AL + off);
            }
            #pragma unroll
            for (int j4 = 0; j4 < 2; j4++) {
                uint32_t off = (uint32_t)((j4 * 16 * SMS + ks * 16) * 2);
                uint32_t bh4[4];
                ldsm4(bh4, bB + off);
                // 2-term split: hi then lo against the same B fragments.
                mma16816(acc[0][2*j4],   afh[0], &bh4[0]);
                mma16816(acc[0][2*j4+1], afh[0], &bh4[2]);
                mma16816(acc[1][2*j4],   afh[1], &bh4[0]);
                mma16816(acc[1][2*j4+1], afh[1], &bh4[2]);

                mma16816(acc[0][2*j4],   afl[0], &bh4[0]);
                mma16816(acc[0][2*j4+1], afl[0], &bh4[2]);
                mma16816(acc[1][2*j4],   afl[1], &bh4[0]);
                mma16816(acc[1][2*j4+1], afl[1], &bh4[2]);
            }
        }
    }

    // Epilogue. d0=(r,c), d1=(r,c+1), d2=(r+8,c), d3=(r+8,c+1);
    // r = lane>>2, c = (lane&3)*2.
    #pragma unroll
    for (int i = 0; i < 2; i++) {
        int gm = m0 + warpM * 32 + i * 16 + (lane >> 2);
        #pragma unroll
        for (int j = 0; j < 4; j++) {
            int gn = n0 + warpN * 32 + j * 8 + (lane & 3) * 2;
            float* d = acc[i][j];
            if (L1) {
                #pragma unroll
                for (int half = 0; half < 2; half++) {
                    int r = gm + half * 8;
                    float v0 = elu1(d[half * 2 + 0]);
                    float v1 = elu1(d[half * 2 + 1]);
                    __half h0 = __float2half_rn(v0), h1 = __float2half_rn(v1);
                    __half l0 = __float2half_rn(v0 - __half2float(h0));
                    __half l1 = __float2half_rn(v1 - __half2float(h1));
                    __half2 hp = __halves2half2(h0, h1);
                    __half2 lp = __halves2half2(l0, l1);
                    size_t off = (size_t)r * ldc + gn;
                    *reinterpret_cast<uint32_t*>(Ch + off) = *(uint32_t*)&hp;
                    *reinterpret_cast<uint32_t*>(Cl + off) = *(uint32_t*)&lp;
                }
            } else {
                size_t off0 = (size_t)gm * ldc + gn;
                size_t off1 = (size_t)(gm + 8) * ldc + gn;
                *reinterpret_cast<float2*>(Cf + off0) = make_float2(d[0], d[1]);
                *reinterpret_cast<float2*>(Cf + off1) = make_float2(d[2], d[3]);
            }
        }
    }

    // Producer publishes completion for its sample.
    if (L1) {
        __syncthreads();
        __threadfence();
        if (tid == 0) atomicAdd(&g_cnt[s], 1);
    }
}

// ---------------------------------------------------------------------------
// Launch
// Inputs: x [1024,512], z [10,8], Wa [10,8], Wb [10,10], Wc [1048576,10], samples
// Output: y [10, 1024, 512] fp32
// ---------------------------------------------------------------------------
extern "C" void kernel_launch(void* const* d_in, const int* in_sizes, int n_in,
                              void* d_out, int out_size) {
    const float* x  = (const float*)d_in[0];
    const float* z  = (const float*)d_in[1];
    const float* Wa = (const float*)d_in[2];
    const float* Wb = (const float*)d_in[3];
    const float* Wc = (const float*)d_in[4];
    float* out = (float*)d_out;
    (void)in_sizes; (void)n_in; (void)out_size;

    __half *xh, *xl, *th, *ah, *al;
    cudaGetSymbolAddress((void**)&xh, g_xh);
    cudaGetSymbolAddress((void**)&xl, g_xl);
    cudaGetSymbolAddress((void**)&th, g_th);
    cudaGetSymbolAddress((void**)&ah, g_ah);
    cudaGetSymbolAddress((void**)&al, g_al);

    static bool attr_done = false;
    if (!attr_done) {
        cudaFuncSetAttribute(fused_gemm_kernel,
                             cudaFuncAttributeMaxDynamicSharedMemorySize, SMEM_BYTES);
        attr_done = true;
    }

    hyper_trunk_kernel<<<1, 128>>>(z, Wa, Wb);
    xconv_kernel<<<(BATCH * IN_DIM / 4 + 255) / 256, 256>>>(x);
    theta_kernel<<<(NPARAMS / 2 + 255) / 256, 256>>>(Wc);

    fused_gemm_kernel<<<L1_CTAS + L2_CTAS, 256, SMEM_BYTES>>>(
        xh, xl, th, ah, al, out);
}

// round 16
// speedup vs baseline: 2.1685x; 1.3076x over previous
#include <cuda_runtime.h>
#include <cuda_fp16.h>
#include <stdint.h>
#include <math.h>

#define S_SAMPLES 10
#define IN_DIM    512
#define HID_DIM   1024
#define OUT_DIM   512
#define BATCH     1024
#define NPARAMS   (HID_DIM*IN_DIM + OUT_DIM*HID_DIM)   // 1,048,576
#define N1        (HID_DIM*IN_DIM)                      // 524,288

// Tile geometry: 64(M) x 128(N) CTA tile, warp tile 32x32 (2M x 4N warps).
#define L1_TILES_PER_S ((BATCH/64) * (HID_DIM/128))   // 128
#define L2_TILES_PER_S ((BATCH/64) * (OUT_DIM/128))   // 64
#define L1_CTAS (S_SAMPLES * L1_TILES_PER_S)          // 1280
#define L2_CTAS (S_SAMPLES * L2_TILES_PER_S)          // 640

// ---------------------------------------------------------------------------
// Scratch (device globals — no allocation allowed)
// Full fp16 path: x, a, theta all single fp16. Calibrated error model:
// W-only rounding measured 2.97e-4; adding A rounding (independent, same
// magnitude) -> ~4.2e-4 total, 2.4x under the 1e-3 threshold.
// ---------------------------------------------------------------------------
static __device__ float g_hm[S_SAMPLES * 10];
static __device__ int   g_cnt[S_SAMPLES];
static __device__ __half g_xh[BATCH * IN_DIM];
static __device__ __half g_th[(size_t)S_SAMPLES * NPARAMS];
static __device__ __half g_ah[(size_t)S_SAMPLES * BATCH * HID_DIM];

__device__ __forceinline__ float elu1(float v) { return v > 0.0f ? v : expm1f(v); }

// ---------------------------------------------------------------------------
// PTX helpers (portable: sm_80+ instructions only)
// ---------------------------------------------------------------------------
__device__ __forceinline__ uint32_t smem_u32(const void* p) {
    uint32_t a;
    asm("{ .reg .u64 t; cvta.to.shared.u64 t, %1; cvt.u32.u64 %0, t; }" : "=r"(a) : "l"(p));
    return a;
}
__device__ __forceinline__ void cp_async16(uint32_t smem_dst, const void* gmem_src) {
    asm volatile("cp.async.cg.shared.global [%0], [%1], 16;"
                 :: "r"(smem_dst), "l"(gmem_src));
}
__device__ __forceinline__ void cp_commit() {
    asm volatile("cp.async.commit_group;");
}
__device__ __forceinline__ void cp_wait0() {
    asm volatile("cp.async.wait_group 0;");
}
__device__ __forceinline__ void ldsm4(uint32_t* r, uint32_t addr) {
    asm volatile("ldmatrix.sync.aligned.m8n8.x4.shared.b16 {%0,%1,%2,%3}, [%4];"
                 : "=r"(r[0]), "=r"(r[1]), "=r"(r[2]), "=r"(r[3]) : "r"(addr));
}
__device__ __forceinline__ void mma16816(float* d, const uint32_t* a, const uint32_t* b) {
    asm volatile("mma.sync.aligned.m16n8k16.row.col.f32.f16.f16.f32 "
                 "{%0,%1,%2,%3}, {%4,%5,%6,%7}, {%8,%9}, {%0,%1,%2,%3};"
                 : "+f"(d[0]), "+f"(d[1]), "+f"(d[2]), "+f"(d[3])
                 : "r"(a[0]), "r"(a[1]), "r"(a[2]), "r"(a[3]), "r"(b[0]), "r"(b[1]));
}

// ---------------------------------------------------------------------------
// Kernel 1: tiny hypernet trunk
// ---------------------------------------------------------------------------
__global__ void hyper_trunk_kernel(const float* __restrict__ z,
                                   const float* __restrict__ Wa,
                                   const float* __restrict__ Wb) {
    __shared__ float h1[S_SAMPLES * 10];
    int tid = threadIdx.x;
    if (tid < S_SAMPLES * 10) {
        int s = tid / 10, w = tid % 10;
        float acc = 0.0f;
        #pragma unroll
        for (int c = 0; c < 8; c++) acc += z[s*8 + c] * Wa[w*8 + c];
        h1[tid] = elu1(acc);
    }
    __syncthreads();
    if (tid < S_SAMPLES * 10) {
        int s = tid / 10, v = tid % 10;
        float acc = 0.0f;
        #pragma unroll
        for (int w = 0; w < 10; w++) acc += h1[s*10 + w] * Wb[v*10 + w];
        g_hm[s*10 + v] = elu1(acc);
    }
}

// ---------------------------------------------------------------------------
// Kernel 2: x -> single fp16
// ---------------------------------------------------------------------------
__global__ void xconv_kernel(const float* __restrict__ x) {
    int i4 = blockIdx.x * blockDim.x + threadIdx.x;
    if (i4 * 4 >= BATCH * IN_DIM) return;
    float4 v = reinterpret_cast<const float4*>(x)[i4];
    __half2 h01 = __halves2half2(__float2half_rn(v.x), __float2half_rn(v.y));
    __half2 h23 = __halves2half2(__float2half_rn(v.z), __float2half_rn(v.w));
    reinterpret_cast<uint2*>(g_xh)[i4] = make_uint2(*(uint32_t*)&h01, *(uint32_t*)&h23);
}

// ---------------------------------------------------------------------------
// Kernel 3: theta -> single fp16. Also zeroes layer1-completion counters.
// ---------------------------------------------------------------------------
__global__ void theta_kernel(const float* __restrict__ Wc) {
    if (blockIdx.x == 0 && threadIdx.x < S_SAMPLES) g_cnt[threadIdx.x] = 0;

    __shared__ float hm_s[S_SAMPLES * 10];
    if (threadIdx.x < S_SAMPLES * 10) hm_s[threadIdx.x] = g_hm[threadIdx.x];
    __syncthreads();

    int p0 = (blockIdx.x * blockDim.x + threadIdx.x) * 2;
    if (p0 >= NPARAMS) return;

    float wc0[10], wc1[10];
    #pragma unroll
    for (int v = 0; v < 10; v++) {
        wc0[v] = Wc[(size_t)p0 * 10 + v];
        wc1[v] = Wc[(size_t)(p0 + 1) * 10 + v];
    }
    #pragma unroll
    for (int s = 0; s < S_SAMPLES; s++) {
        float a0 = 0.0f, a1 = 0.0f;
        #pragma unroll
        for (int v = 0; v < 10; v++) {
            a0 += hm_s[s*10 + v] * wc0[v];
            a1 += hm_s[s*10 + v] * wc1[v];
        }
        __half2 hp = __halves2half2(__float2half_rn(a0), __float2half_rn(a1));
        *reinterpret_cast<uint32_t*>(g_th + (size_t)s * NPARAMS + p0) = *(uint32_t*)&hp;
    }
}

// ---------------------------------------------------------------------------
// Fused GEMM kernel: one flat grid of 1920 CTAs.
//   bx in [0, 1280):    layer1 tile — a[s] = elu(x @ W1[s]^T), K=512 (16 chunks)
//   bx in [1280, 1920): layer2 tile — y[s] = a[s] @ W2[s]^T,  K=1024 (32 chunks)
// Layer2 CTAs spin on g_cnt[s]==128 before their first load (deadlock-free by
// linear dispatch order).
//
// GEMM body: mma.sync NT full fp16 — ONE MMA per product (the HMMA rate
// ceiling at ~50% tensor means runtime ∝ MMA count; this is the lever).
// 64x128 CTA tile, 8 warps (2Mx4N), warp tile 32x32, KC=32, 2-stage
// cp.async, one __syncthreads per chunk, 3 CTAs/SM. SMS=40: 80B stride.
// Stage = (64 A + 128 B) rows * 80B = 15360B; 2 stages = 30720B/CTA.
// ---------------------------------------------------------------------------
#define KC      32
#define SMS     40
#define TA_E    (64 * SMS)               // A tile elems (2560)
#define TB_E    (128 * SMS)              // B tile elems (5120)
#define STAGE_B ((TA_E + TB_E) * 2)      // 15360 B
#define SMEM_BYTES (2 * STAGE_B)         // 30720
#define OFF_B   (TA_E * 2)

__global__ __launch_bounds__(256, 3)
void fused_gemm_kernel(const __half* __restrict__ xh,
                       const __half* __restrict__ th,
                       __half* __restrict__ ah,
                       float* __restrict__ out) {
    extern __shared__ __half sm[];
    const uint32_t smb = smem_u32(sm);
    const int tid  = threadIdx.x;
    const int lane = tid & 31, wid = tid >> 5;
    const int warpM = wid & 1, warpN = wid >> 1;   // 2M x 4N
    const int bx = blockIdx.x;
    const bool L1 = bx < L1_CTAS;

    int s, m0, n0, lda, ldb, ldc, NC;
    const __half *Ah_, *Bh_;
    __half *Ch = nullptr;
    float* Cf = nullptr;

    if (L1) {
        s = bx / L1_TILES_PER_S;
        int t = bx % L1_TILES_PER_S;
        m0 = (t >> 3) * 64;  n0 = (t & 7) * 128;
        Ah_ = xh;  lda = IN_DIM;
        Bh_ = th + (size_t)s * NPARAMS;  ldb = IN_DIM;
        Ch = ah + (size_t)s * BATCH * HID_DIM;
        ldc = HID_DIM;  NC = 16;
    } else {
        int idx = bx - L1_CTAS;
        s = idx / L2_TILES_PER_S;
        int t = idx % L2_TILES_PER_S;
        m0 = (t >> 2) * 64;  n0 = (t & 3) * 128;
        Ah_ = ah + (size_t)s * BATCH * HID_DIM;  lda = HID_DIM;
        Bh_ = th + (size_t)s * NPARAMS + N1;     ldb = HID_DIM;
        Cf = out + (size_t)s * BATCH * OUT_DIM;
        ldc = OUT_DIM;  NC = 32;

        // Wait for this sample's layer1 to complete before any load.
        if (tid == 0) {
            while (*(volatile int*)&g_cnt[s] < L1_TILES_PER_S) __nanosleep(128);
        }
        __syncthreads();
        __threadfence();   // acquire: order subsequent loads after the flag read
    }

    // Producer mapping.
    // A: 256 threads cover 64 rows x 4 col-chunks of 8 elems; 1 cp16 each.
    const int par = tid >> 2;               // 0..63
    const int pav = (tid & 3) * 8;          // 0,8,16,24
    const __half* pAh = Ah_ + (size_t)(m0 + par) * lda + pav;
    const uint32_t pdA = smb + (uint32_t)(par * SMS + pav) * 2;
    // B: 256 threads cover 128 rows x 2 halves of 16 elems; 2 cp16 each.
    const int pbr = tid >> 1;               // 0..127
    const int pbv = (tid & 1) * 16;         // 0 or 16
    const __half* pBh = Bh_ + (size_t)(n0 + pbr) * ldb + pbv;
    const uint32_t pdB = smb + (uint32_t)(pbr * SMS + pbv) * 2;

    // Consumer (ldmatrix) base addresses, hoisted.
    const uint32_t aOff = smb + (uint32_t)(((warpM * 32 + (lane & 15)) * SMS
                                            + ((lane >> 4) << 3)) * 2);
    const int rr = (lane & 7) + ((lane >> 4) & 1) * 8;
    const int kh = (lane >> 3) & 1;
    const uint32_t bOff = smb + OFF_B
                        + (uint32_t)(((warpN * 32 + rr) * SMS + kh * 8) * 2);

    float acc[2][4][4];
    #pragma unroll
    for (int i = 0; i < 2; i++)
        #pragma unroll
        for (int j = 0; j < 4; j++)
            #pragma unroll
            for (int q = 0; q < 4; q++) acc[i][j][q] = 0.0f;

    auto issue = [&](int stage, int k0) {
        const uint32_t so = (uint32_t)stage * STAGE_B;
        cp_async16(pdA + so, pAh + k0);
        cp_async16(pdB + so + OFF_B,      pBh + k0);
        cp_async16(pdB + so + OFF_B + 16, pBh + k0 + 8);
        cp_commit();
    };

    issue(0, 0);

    for (int c = 0; c < NC; c++) {
        cp_wait0();
        __syncthreads();
        if (c + 1 < NC) issue((c + 1) & 1, (c + 1) * KC);

        const uint32_t aB = aOff + (uint32_t)(c & 1) * STAGE_B;
        const uint32_t bB = bOff + (uint32_t)(c & 1) * STAGE_B;
        #pragma unroll
        for (int ks = 0; ks < 2; ks++) {
            uint32_t af[2][4];
            #pragma unroll
            for (int i = 0; i < 2; i++) {
                uint32_t off = (uint32_t)((i * 16 * SMS + ks * 16) * 2);
                ldsm4(af[i], aB + off);
            }
            #pragma unroll
            for (int j4 = 0; j4 < 2; j4++) {
                uint32_t off = (uint32_t)((j4 * 16 * SMS + ks * 16) * 2);
                uint32_t bh4[4];
                ldsm4(bh4, bB + off);
                mma16816(acc[0][2*j4],   af[0], &bh4[0]);
                mma16816(acc[0][2*j4+1], af[0], &bh4[2]);
                mma16816(acc[1][2*j4],   af[1], &bh4[0]);
                mma16816(acc[1][2*j4+1], af[1], &bh4[2]);
            }
        }
    }

    // Epilogue. d0=(r,c), d1=(r,c+1), d2=(r+8,c), d3=(r+8,c+1);
    // r = lane>>2, c = (lane&3)*2.
    #pragma unroll
    for (int i = 0; i < 2; i++) {
        int gm = m0 + warpM * 32 + i * 16 + (lane >> 2);
        #pragma unroll
        for (int j = 0; j < 4; j++) {
            int gn = n0 + warpN * 32 + j * 8 + (lane & 3) * 2;
            float* d = acc[i][j];
            if (L1) {
                #pragma unroll
                for (int half = 0; half < 2; half++) {
                    int r = gm + half * 8;
                    float v0 = elu1(d[half * 2 + 0]);
                    float v1 = elu1(d[half * 2 + 1]);
                    __half2 hp = __halves2half2(__float2half_rn(v0), __float2half_rn(v1));
                    *reinterpret_cast<uint32_t*>(Ch + (size_t)r * ldc + gn) = *(uint32_t*)&hp;
                }
            } else {
                size_t off0 = (size_t)gm * ldc + gn;
                size_t off1 = (size_t)(gm + 8) * ldc + gn;
                *reinterpret_cast<float2*>(Cf + off0) = make_float2(d[0], d[1]);
                *reinterpret_cast<float2*>(Cf + off1) = make_float2(d[2], d[3]);
            }
        }
    }

    // Producer publishes completion for its sample.
    if (L1) {
        __syncthreads();
        __threadfence();
        if (tid == 0) atomicAdd(&g_cnt[s], 1);
    }
}

// ---------------------------------------------------------------------------
// Launch
// Inputs: x [1024,512], z [10,8], Wa [10,8], Wb [10,10], Wc [1048576,10], samples
// Output: y [10, 1024, 512] fp32
// ---------------------------------------------------------------------------
extern "C" void kernel_launch(void* const* d_in, const int* in_sizes, int n_in,
                              void* d_out, int out_size) {
    const float* x  = (const float*)d_in[0];
    const float* z  = (const float*)d_in[1];
    const float* Wa = (const float*)d_in[2];
    const float* Wb = (const float*)d_in[3];
    const float* Wc = (const float*)d_in[4];
    float* out = (float*)d_out;
    (void)in_sizes; (void)n_in; (void)out_size;

    __half *xh, *th, *ah;
    cudaGetSymbolAddress((void**)&xh, g_xh);
    cudaGetSymbolAddress((void**)&th, g_th);
    cudaGetSymbolAddress((void**)&ah, g_ah);

    static bool attr_done = false;
    if (!attr_done) {
        cudaFuncSetAttribute(fused_gemm_kernel,
                             cudaFuncAttributeMaxDynamicSharedMemorySize, SMEM_BYTES);
        attr_done = true;
    }

    hyper_trunk_kernel<<<1, 128>>>(z, Wa, Wb);
    xconv_kernel<<<(BATCH * IN_DIM / 4 + 255) / 256, 256>>>(x);
    theta_kernel<<<(NPARAMS / 2 + 255) / 256, 256>>>(Wc);

    fused_gemm_kernel<<<L1_CTAS + L2_CTAS, 256, SMEM_BYTES>>>(
        xh, th, ah, out);
}